// round 1
// baseline (speedup 1.0000x reference)
#include <cuda_runtime.h>
#include <math.h>

#define H 128
#define KN 20
#define NB 65536          // batch B
#define NEGV (-1e9f)

// ---------------- device scratch (no allocations allowed) ----------------
__device__ float g_A[129 * 128];          // segment slope rows
__device__ float g_C[129 * 128];          // segment intercept rows (includes tp_b2)
__device__ float g_bp[128];               // sorted breakpoints
__device__ float g_z[2u * NB * 128];      // zu | zv  (67 MB)

// =========================================================================
// Kernel 1: piecewise-linear decomposition of the time-encoder MLP.
// time_e(delta) = A[seg]*delta + C[seg], seg = #breakpoints < delta.
// One block, 128 threads. Thread h = neuron for sort, thread d = dim for prefix.
// =========================================================================
__global__ void precompute_kernel(const float* __restrict__ tp_w1,
                                  const float* __restrict__ tp_b1,
                                  const float* __restrict__ tp_w2,
                                  const float* __restrict__ tp_b2)
{
    __shared__ float sw[128], sb[128], sbp[128];
    __shared__ int   sorder[128];

    int h = threadIdx.x;
    float w = tp_w1[h], b = tp_b1[h];
    float bp = (w != 0.0f) ? (-b / w) : INFINITY;
    sw[h] = w; sb[h] = b; sbp[h] = bp;
    __syncthreads();

    // rank sort (O(128^2) total, trivial)
    int r = 0;
    for (int j = 0; j < 128; j++) {
        float bj = sbp[j];
        if (bj < bp || (bj == bp && j < h)) r++;
    }
    sorder[r] = h;
    __syncthreads();
    g_bp[h] = sbp[sorder[h]];

    // prefix accumulation over dims; thread d owns output dim d
    int d = h;
    float a = 0.0f;
    float c = tp_b2[d];
    for (int j = 0; j < 128; j++) {
        float wj = sw[j];
        // active in leftmost segment: w<0 neurons (delta < bp), or w==0 && b>0 (always on)
        if (wj < 0.0f || (wj == 0.0f && sb[j] > 0.0f)) {
            float w2v = tp_w2[j * 128 + d];
            a += wj * w2v;
            c += sb[j] * w2v;
        }
    }
    g_A[d] = a;
    g_C[d] = c;
    for (int s = 1; s <= 128; s++) {
        int j = sorder[s - 1];
        float wj = sw[j];
        float w2v = tp_w2[j * 128 + d];
        if (wj > 0.0f)      { a += wj * w2v; c += sb[j] * w2v; }  // turns on
        else if (wj < 0.0f) { a -= wj * w2v; c -= sb[j] * w2v; }  // turns off
        g_A[s * 128 + d] = a;
        g_C[s * 128 + d] = c;
    }
}

// =========================================================================
// Kernel 2: temporal attention encoder. One warp per (edge, side).
// keys staged in shared memory, scores/softmax in registers.
// =========================================================================
__global__ void __launch_bounds__(128) encode_kernel(
    const int*   __restrict__ edge_index,
    const int*   __restrict__ ets,
    const int*   __restrict__ hnb,
    const int*   __restrict__ hts,
    const int*   __restrict__ hsg,
    const float* __restrict__ nemb,
    const float* __restrict__ semb)
{
    __shared__ float skeys[4][KN][128];
    __shared__ float sbp[128];

    sbp[threadIdx.x] = g_bp[threadIdx.x];
    __syncthreads();

    const int w    = threadIdx.x >> 5;
    const int lane = threadIdx.x & 31;
    const int task = blockIdx.x * 4 + w;     // 2*NB tasks, divisible by 4
    const int e    = task >> 1;
    const int side = task & 1;

    const int node = edge_index[side * NB + e];
    const int qt   = ets[e];
    const float qtf = (float)qt;

    const float4* nemb4 = (const float4*)nemb;
    const float4* semb4 = (const float4*)semb;
    const float4* A4 = (const float4*)g_A;
    const float4* C4 = (const float4*)g_C;

    const float4 q4 = __ldg(&nemb4[node * 32 + lane]);

    int nb_l = -1, ht_l = 0, sg_l = 0;
    if (lane < KN) {
        nb_l = hnb[node * KN + lane];
        ht_l = hts[node * KN + lane];
        sg_l = hsg[node * KN + lane];
    }

    float sc[KN];
    const float rsH = 0.08838834764831845f;   // 1/sqrt(128)

    #pragma unroll
    for (int k = 0; k < KN; k++) {
        const int nb = __shfl_sync(0xffffffffu, nb_l, k);
        const int ht = __shfl_sync(0xffffffffu, ht_l, k);
        const int sg = __shfl_sync(0xffffffffu, sg_l, k);

        const float delta = qtf - (float)ht;

        // segment = #(sorted breakpoints < delta); 7-step binary search in smem
        int lo = 0, hi = 128;
        #pragma unroll
        for (int it = 0; it < 7; it++) {
            int mid = (lo + hi) >> 1;
            if (sbp[mid] < delta) lo = mid + 1; else hi = mid;
        }
        const int seg = lo;

        const int nbc = (nb == -1) ? 0 : nb;
        const float4 em = __ldg(&nemb4[nbc * 32 + lane]);
        const float4 s4 = __ldg(&semb4[sg * 32 + lane]);
        const float4 a4 = A4[seg * 32 + lane];
        const float4 c4 = C4[seg * 32 + lane];

        const float kx = em.x + s4.x + (a4.x * delta + c4.x);
        const float ky = em.y + s4.y + (a4.y * delta + c4.y);
        const float kz = em.z + s4.z + (a4.z * delta + c4.z);
        const float kw = em.w + s4.w + (a4.w * delta + c4.w);

        *((float4*)&skeys[w][k][lane * 4]) = make_float4(kx, ky, kz, kw);

        float dp = kx * q4.x + ky * q4.y + kz * q4.z + kw * q4.w;
        #pragma unroll
        for (int off = 16; off > 0; off >>= 1)
            dp += __shfl_xor_sync(0xffffffffu, dp, off);

        const bool valid = (nb != -1) && (ht < qt);
        sc[k] = valid ? dp * rsH : NEGV;
    }

    // softmax over K (replicated on all lanes)
    float m = sc[0];
    #pragma unroll
    for (int k = 1; k < KN; k++) m = fmaxf(m, sc[k]);
    float s = 0.0f;
    float wk[KN];
    #pragma unroll
    for (int k = 0; k < KN; k++) { wk[k] = expf(sc[k] - m); s += wk[k]; }
    const float inv = 1.0f / s;

    float4 acc = make_float4(0.f, 0.f, 0.f, 0.f);
    #pragma unroll
    for (int k = 0; k < KN; k++) {
        const float ww = wk[k] * inv;
        const float4 kv = *((const float4*)&skeys[w][k][lane * 4]);
        acc.x += ww * kv.x;
        acc.y += ww * kv.y;
        acc.z += ww * kv.z;
        acc.w += ww * kv.w;
    }
    ((float4*)g_z)[(side * NB + e) * 32 + lane] = acc;
}

// =========================================================================
// Kernel 3: fused final MLP. logits = relu(feat @ W1 + b1) @ w2 + b2
// feat = [zu, zv, |zu-zv|, zu*zv]  => M=65536, N=128, K=512 GEMM + epilogue.
// 128x128 tile / block, 256 threads, 8x8 microtile, packed f32x2 FMA.
// =========================================================================
__device__ __forceinline__ unsigned long long ffma2(unsigned long long a,
                                                    unsigned long long b,
                                                    unsigned long long c)
{
    unsigned long long d;
    asm("fma.rn.f32x2 %0, %1, %2, %3;" : "=l"(d) : "l"(a), "l"(b), "l"(c));
    return d;
}
__device__ __forceinline__ unsigned long long pack2(float x, float y)
{
    unsigned long long r;
    asm("mov.b64 %0, {%1, %2};" : "=l"(r) : "f"(x), "f"(y));
    return r;
}
__device__ __forceinline__ float2 unpack2(unsigned long long v)
{
    float2 r;
    asm("mov.b64 {%0, %1}, %2;" : "=f"(r.x), "=f"(r.y) : "l"(v));
    return r;
}

__global__ void __launch_bounds__(256) mlp_kernel(
    const float* __restrict__ w1,   // [512,128] row-major [in,out]
    const float* __restrict__ b1,   // [128]
    const float* __restrict__ w2,   // [128]
    const float* __restrict__ b2,   // [1]
    float*       __restrict__ out)  // [NB]
{
    __shared__ float sF[128][33];   // feat tile, transposed-friendly padded
    __shared__ float sW[32][128];   // W1 chunk
    __shared__ float slog[128];

    const int tid = threadIdx.x;
    const int tx = tid & 15;        // n-group
    const int ty = tid >> 4;        // m-group
    const int e0 = blockIdx.x * 128;

    if (tid < 128) slog[tid] = 0.0f;

    unsigned long long acc2[8][4];
    #pragma unroll
    for (int mi = 0; mi < 8; mi++)
        #pragma unroll
        for (int nj = 0; nj < 4; nj++)
            acc2[mi][nj] = 0ULL;

    for (int kc = 0; kc < 16; kc++) {
        const int region = kc >> 2;       // 0:zu 1:zv 2:|zu-zv| 3:zu*zv
        const int ii0 = (kc & 3) * 32;
        const int i0 = kc * 32;

        __syncthreads();
        // stage feat chunk: sF[m][i]
        {
            const int i = tid & 31;
            const int m0 = (tid >> 5) * 16;
            #pragma unroll
            for (int r = 0; r < 16; r++) {
                const int m = m0 + r;
                const float a  = g_z[(unsigned)(e0 + m) * 128 + ii0 + i];
                const float bv = g_z[(unsigned)(NB + e0 + m) * 128 + ii0 + i];
                float v;
                if (region == 0)      v = a;
                else if (region == 1) v = bv;
                else if (region == 2) v = fabsf(a - bv);
                else                  v = a * bv;
                sF[m][i] = v;
            }
        }
        // stage W1 chunk: sW[i][n]
        {
            #pragma unroll
            for (int r = 0; r < 16; r++) {
                const int idx = tid + 256 * r;
                const int i = idx >> 7;
                const int n = idx & 127;
                sW[i][n] = w1[(i0 + i) * 128 + n];
            }
        }
        __syncthreads();

        #pragma unroll
        for (int i = 0; i < 32; i++) {
            unsigned long long av[8];
            #pragma unroll
            for (int mi = 0; mi < 8; mi++) {
                const float a = sF[ty * 8 + mi][i];
                av[mi] = pack2(a, a);
            }
            const float4 bA = *((const float4*)&sW[i][tx * 8]);
            const float4 bB = *((const float4*)&sW[i][tx * 8 + 4]);
            unsigned long long bv[4];
            bv[0] = pack2(bA.x, bA.y);
            bv[1] = pack2(bA.z, bA.w);
            bv[2] = pack2(bB.x, bB.y);
            bv[3] = pack2(bB.z, bB.w);
            #pragma unroll
            for (int mi = 0; mi < 8; mi++)
                #pragma unroll
                for (int nj = 0; nj < 4; nj++)
                    acc2[mi][nj] = ffma2(av[mi], bv[nj], acc2[mi][nj]);
        }
    }

    // epilogue: hid = relu(acc + b1); partial logit = hid . w2
    float b1v[8], w2v[8];
    #pragma unroll
    for (int u = 0; u < 8; u++) {
        b1v[u] = b1[tx * 8 + u];
        w2v[u] = w2[tx * 8 + u];
    }
    #pragma unroll
    for (int mi = 0; mi < 8; mi++) {
        float p = 0.0f;
        #pragma unroll
        for (int nj = 0; nj < 4; nj++) {
            const float2 v = unpack2(acc2[mi][nj]);
            const float h0 = fmaxf(v.x + b1v[2 * nj],     0.0f);
            const float h1 = fmaxf(v.y + b1v[2 * nj + 1], 0.0f);
            p += h0 * w2v[2 * nj] + h1 * w2v[2 * nj + 1];
        }
        atomicAdd(&slog[ty * 8 + mi], p);
    }
    __syncthreads();
    if (tid < 128) out[e0 + tid] = slog[tid] + b2[0];
}

// =========================================================================
extern "C" void kernel_launch(void* const* d_in, const int* in_sizes, int n_in,
                              void* d_out, int out_size)
{
    const int*   edge_index = (const int*)  d_in[0];
    const int*   ets        = (const int*)  d_in[1];
    const int*   hnb        = (const int*)  d_in[2];
    const int*   hts        = (const int*)  d_in[3];
    const int*   hsg        = (const int*)  d_in[4];
    const float* nemb       = (const float*)d_in[5];
    const float* semb       = (const float*)d_in[6];
    const float* tp_w1      = (const float*)d_in[7];
    const float* tp_b1      = (const float*)d_in[8];
    const float* tp_w2      = (const float*)d_in[9];
    const float* tp_b2      = (const float*)d_in[10];
    const float* em_w1      = (const float*)d_in[11];
    const float* em_b1      = (const float*)d_in[12];
    const float* em_w2      = (const float*)d_in[13];
    const float* em_b2      = (const float*)d_in[14];
    float* out = (float*)d_out;

    precompute_kernel<<<1, 128>>>(tp_w1, tp_b1, tp_w2, tp_b2);
    encode_kernel<<<(2 * NB) / 4, 128>>>(edge_index, ets, hnb, hts, hsg, nemb, semb);
    mlp_kernel<<<NB / 128, 256>>>(em_w1, em_b1, em_w2, em_b2, out);
}

// round 2
// speedup vs baseline: 1.4806x; 1.4806x over previous
#include <cuda_runtime.h>
#include <math.h>

#define H 128
#define KN 20
#define NB 65536          // batch B
#define NEGV (-1e9f)

// ---------------- device scratch (no allocations allowed) ----------------
__device__ float g_A[129 * 128];          // segment slope rows
__device__ float g_C[129 * 128];          // segment intercept rows (includes tp_b2)
__device__ float g_bp[128];               // sorted breakpoints
__device__ float g_z[2u * NB * 128];      // zu | zv  (67 MB)

// =========================================================================
// Kernel 1: piecewise-linear decomposition of the time-encoder MLP.
// time_e(delta) = A[seg]*delta + C[seg], seg = #(sorted breakpoints < delta).
// Parallel version: one block per segment (129 blocks x 128 threads).
// Neuron j is active in segment s iff:
//   w_j > 0  and rank_j <  s
//   w_j < 0  and rank_j >= s
//   w_j == 0 and b_j > 0
// =========================================================================
__global__ void precompute_kernel(const float* __restrict__ tp_w1,
                                  const float* __restrict__ tp_b1,
                                  const float* __restrict__ tp_w2,
                                  const float* __restrict__ tp_b2)
{
    __shared__ float sw[128], sb[128], sbp[128];
    __shared__ int   srank[128];

    const int h = threadIdx.x;
    const float w = tp_w1[h], b = tp_b1[h];
    const float bp = (w != 0.0f) ? (-b / w) : INFINITY;
    sw[h] = w; sb[h] = b; sbp[h] = bp;
    __syncthreads();

    // rank of neuron h among breakpoints (stable by index)
    int r = 0;
    #pragma unroll 8
    for (int j = 0; j < 128; j++) {
        const float bj = sbp[j];
        if (bj < bp || (bj == bp && j < h)) r++;
    }
    srank[h] = r;
    if (blockIdx.x == 0) g_bp[r] = bp;   // sorted breakpoints (block 0 only)
    __syncthreads();

    const int s = blockIdx.x;            // segment id 0..128
    const int d = h;                     // output dim owned by this thread
    float a = 0.0f;
    float c = tp_b2[d];
    #pragma unroll 4
    for (int j = 0; j < 128; j++) {
        const float wj = sw[j];
        bool active;
        if (wj > 0.0f)      active = (srank[j] < s);
        else if (wj < 0.0f) active = (srank[j] >= s);
        else                active = (sb[j] > 0.0f);
        if (active) {
            const float w2v = __ldg(&tp_w2[j * 128 + d]);
            a += wj * w2v;
            c += sb[j] * w2v;
        }
    }
    g_A[s * 128 + d] = a;
    g_C[s * 128 + d] = c;
}

// =========================================================================
// Kernel 2: temporal attention encoder with ONLINE SOFTMAX (single pass).
// One warp per (edge, side); 8 warps per block; no key staging in smem.
// =========================================================================
__global__ void __launch_bounds__(256) encode_kernel(
    const int*   __restrict__ edge_index,
    const int*   __restrict__ ets,
    const int*   __restrict__ hnb,
    const int*   __restrict__ hts,
    const int*   __restrict__ hsg,
    const float* __restrict__ nemb,
    const float* __restrict__ semb)
{
    __shared__ float sbp[128];
    if (threadIdx.x < 128) sbp[threadIdx.x] = g_bp[threadIdx.x];
    __syncthreads();

    const int w    = threadIdx.x >> 5;
    const int lane = threadIdx.x & 31;
    const int task = blockIdx.x * 8 + w;     // 2*NB tasks, divisible by 8
    const int e    = task >> 1;
    const int side = task & 1;

    const int node = edge_index[side * NB + e];
    const int qt   = ets[e];
    const float qtf = (float)qt;

    const float4* nemb4 = (const float4*)nemb;
    const float4* semb4 = (const float4*)semb;
    const float4* A4 = (const float4*)g_A;
    const float4* C4 = (const float4*)g_C;

    const float4 q4 = __ldg(&nemb4[node * 32 + lane]);

    int nb_l = -1, ht_l = 0, sg_l = 0;
    if (lane < KN) {
        nb_l = hnb[node * KN + lane];
        ht_l = hts[node * KN + lane];
        sg_l = hsg[node * KN + lane];
    }

    const float rsH = 0.08838834764831845f;   // 1/sqrt(128)

    float m = -INFINITY;
    float ssum = 0.0f;
    float4 acc = make_float4(0.f, 0.f, 0.f, 0.f);

    #pragma unroll
    for (int k = 0; k < KN; k++) {
        const int nb = __shfl_sync(0xffffffffu, nb_l, k);
        const int ht = __shfl_sync(0xffffffffu, ht_l, k);
        const int sg = __shfl_sync(0xffffffffu, sg_l, k);

        const float delta = qtf - (float)ht;

        // segment = #(sorted breakpoints < delta); 7-step binary search (broadcast LDS)
        int lo = 0, hi = 128;
        #pragma unroll
        for (int it = 0; it < 7; it++) {
            const int mid = (lo + hi) >> 1;
            if (sbp[mid] < delta) lo = mid + 1; else hi = mid;
        }
        const int seg = lo;

        const int nbc = (nb == -1) ? 0 : nb;
        const float4 em = __ldg(&nemb4[nbc * 32 + lane]);
        const float4 s4 = __ldg(&semb4[sg * 32 + lane]);
        const float4 a4 = A4[seg * 32 + lane];
        const float4 c4 = C4[seg * 32 + lane];

        const float kx = em.x + s4.x + fmaf(a4.x, delta, c4.x);
        const float ky = em.y + s4.y + fmaf(a4.y, delta, c4.y);
        const float kz = em.z + s4.z + fmaf(a4.z, delta, c4.z);
        const float kw = em.w + s4.w + fmaf(a4.w, delta, c4.w);

        float dp = kx * q4.x + ky * q4.y + kz * q4.z + kw * q4.w;
        #pragma unroll
        for (int off = 16; off > 0; off >>= 1)
            dp += __shfl_xor_sync(0xffffffffu, dp, off);

        const bool valid = (nb != -1) && (ht < qt);
        const float sc = valid ? dp * rsH : NEGV;

        // online softmax update
        const float mn = fmaxf(m, sc);
        const float f  = __expf(m - mn);    // 0 when m == -inf
        const float we = __expf(sc - mn);
        ssum = ssum * f + we;
        acc.x = acc.x * f + we * kx;
        acc.y = acc.y * f + we * ky;
        acc.z = acc.z * f + we * kz;
        acc.w = acc.w * f + we * kw;
        m = mn;
    }

    const float inv = 1.0f / ssum;
    acc.x *= inv; acc.y *= inv; acc.z *= inv; acc.w *= inv;
    ((float4*)g_z)[(unsigned)(side * NB + e) * 32 + lane] = acc;
}

// =========================================================================
// Kernel 3: fused final MLP. logits = relu(feat @ W1 + b1) @ w2 + b2
// feat = [zu, zv, |zu-zv|, zu*zv]  => M=65536, N=128, K=512 GEMM + epilogue.
// 128x128 tile / block, 256 threads, 8x8 microtile, packed f32x2 FMA.
// Loop order (chunk, region) so zu/zv chunk loads hit L1 across regions.
// =========================================================================
__device__ __forceinline__ unsigned long long ffma2(unsigned long long a,
                                                    unsigned long long b,
                                                    unsigned long long c)
{
    unsigned long long d;
    asm("fma.rn.f32x2 %0, %1, %2, %3;" : "=l"(d) : "l"(a), "l"(b), "l"(c));
    return d;
}
__device__ __forceinline__ unsigned long long pack2(float x, float y)
{
    unsigned long long r;
    asm("mov.b64 %0, {%1, %2};" : "=l"(r) : "f"(x), "f"(y));
    return r;
}
__device__ __forceinline__ float2 unpack2(unsigned long long v)
{
    float2 r;
    asm("mov.b64 {%0, %1}, %2;" : "=f"(r.x), "=f"(r.y) : "l"(v));
    return r;
}

__global__ void __launch_bounds__(256) mlp_kernel(
    const float* __restrict__ w1,   // [512,128] row-major [in,out]
    const float* __restrict__ b1,   // [128]
    const float* __restrict__ w2,   // [128]
    const float* __restrict__ b2,   // [1]
    float*       __restrict__ out)  // [NB]
{
    __shared__ float sF[128][33];   // feat tile (padded)
    __shared__ float sW[32][128];   // W1 chunk
    __shared__ float slog[128];

    const int tid = threadIdx.x;
    const int tx = tid & 15;        // n-group
    const int ty = tid >> 4;        // m-group
    const int e0 = blockIdx.x * 128;

    if (tid < 128) slog[tid] = 0.0f;

    unsigned long long acc2[8][4];
    #pragma unroll
    for (int mi = 0; mi < 8; mi++)
        #pragma unroll
        for (int nj = 0; nj < 4; nj++)
            acc2[mi][nj] = 0ULL;

    for (int ii = 0; ii < 4; ii++) {           // 32-dim chunk within a region
        for (int region = 0; region < 4; region++) {  // 0:zu 1:zv 2:|zu-zv| 3:zu*zv
            const int ii0 = ii * 32;
            const int i0 = region * 128 + ii0; // W1 row offset (k index)

            __syncthreads();
            // stage feat chunk: sF[m][i]
            {
                const int i = tid & 31;
                const int m0 = (tid >> 5) * 16;
                #pragma unroll
                for (int r = 0; r < 16; r++) {
                    const int m = m0 + r;
                    float v;
                    if (region == 0) {
                        v = g_z[(unsigned)(e0 + m) * 128 + ii0 + i];
                    } else if (region == 1) {
                        v = g_z[(unsigned)(NB + e0 + m) * 128 + ii0 + i];
                    } else {
                        const float a  = g_z[(unsigned)(e0 + m) * 128 + ii0 + i];
                        const float bv = g_z[(unsigned)(NB + e0 + m) * 128 + ii0 + i];
                        v = (region == 2) ? fabsf(a - bv) : a * bv;
                    }
                    sF[m][i] = v;
                }
            }
            // stage W1 chunk: sW[i][n]
            {
                #pragma unroll
                for (int r = 0; r < 16; r++) {
                    const int idx = tid + 256 * r;
                    const int i = idx >> 7;
                    const int n = idx & 127;
                    sW[i][n] = w1[(i0 + i) * 128 + n];
                }
            }
            __syncthreads();

            #pragma unroll
            for (int i = 0; i < 32; i++) {
                unsigned long long av[8];
                #pragma unroll
                for (int mi = 0; mi < 8; mi++) {
                    const float a = sF[ty * 8 + mi][i];
                    av[mi] = pack2(a, a);
                }
                const float4 bA = *((const float4*)&sW[i][tx * 8]);
                const float4 bB = *((const float4*)&sW[i][tx * 8 + 4]);
                unsigned long long bv[4];
                bv[0] = pack2(bA.x, bA.y);
                bv[1] = pack2(bA.z, bA.w);
                bv[2] = pack2(bB.x, bB.y);
                bv[3] = pack2(bB.z, bB.w);
                #pragma unroll
                for (int mi = 0; mi < 8; mi++)
                    #pragma unroll
                    for (int nj = 0; nj < 4; nj++)
                        acc2[mi][nj] = ffma2(av[mi], bv[nj], acc2[mi][nj]);
            }
        }
    }

    // epilogue: hid = relu(acc + b1); partial logit = hid . w2
    float b1v[8], w2v[8];
    #pragma unroll
    for (int u = 0; u < 8; u++) {
        b1v[u] = b1[tx * 8 + u];
        w2v[u] = w2[tx * 8 + u];
    }
    #pragma unroll
    for (int mi = 0; mi < 8; mi++) {
        float p = 0.0f;
        #pragma unroll
        for (int nj = 0; nj < 4; nj++) {
            const float2 v = unpack2(acc2[mi][nj]);
            const float h0 = fmaxf(v.x + b1v[2 * nj],     0.0f);
            const float h1 = fmaxf(v.y + b1v[2 * nj + 1], 0.0f);
            p += h0 * w2v[2 * nj] + h1 * w2v[2 * nj + 1];
        }
        atomicAdd(&slog[ty * 8 + mi], p);
    }
    __syncthreads();
    if (tid < 128) out[e0 + tid] = slog[tid] + b2[0];
}

// =========================================================================
extern "C" void kernel_launch(void* const* d_in, const int* in_sizes, int n_in,
                              void* d_out, int out_size)
{
    const int*   edge_index = (const int*)  d_in[0];
    const int*   ets        = (const int*)  d_in[1];
    const int*   hnb        = (const int*)  d_in[2];
    const int*   hts        = (const int*)  d_in[3];
    const int*   hsg        = (const int*)  d_in[4];
    const float* nemb       = (const float*)d_in[5];
    const float* semb       = (const float*)d_in[6];
    const float* tp_w1      = (const float*)d_in[7];
    const float* tp_b1      = (const float*)d_in[8];
    const float* tp_w2      = (const float*)d_in[9];
    const float* tp_b2      = (const float*)d_in[10];
    const float* em_w1      = (const float*)d_in[11];
    const float* em_b1      = (const float*)d_in[12];
    const float* em_w2      = (const float*)d_in[13];
    const float* em_b2      = (const float*)d_in[14];
    float* out = (float*)d_out;

    precompute_kernel<<<129, 128>>>(tp_w1, tp_b1, tp_w2, tp_b2);
    encode_kernel<<<(2 * NB) / 8, 256>>>(edge_index, ets, hnb, hts, hsg, nemb, semb);
    mlp_kernel<<<NB / 128, 256>>>(em_w1, em_b1, em_w2, em_b2, out);
}

// round 3
// speedup vs baseline: 1.8085x; 1.2215x over previous
#include <cuda_runtime.h>
#include <math.h>

#define H 128
#define KN 20
#define NB 65536          // batch B
#define NEGV (-1e9f)

// ---------------- device scratch (no allocations allowed) ----------------
__device__ float g_A[129 * 128];          // segment slope rows
__device__ float g_C[129 * 128];          // segment intercept rows (includes tp_b2)
__device__ float g_bp[128];               // sorted breakpoints
__device__ float g_z[2u * NB * 128];      // zu | zv  (67 MB)

// =========================================================================
// Kernel 1: piecewise-linear decomposition of the time-encoder MLP.
// time_e(delta) = A[seg]*delta + C[seg], seg = #(sorted breakpoints < delta).
// 129 blocks (one per segment) x 256 threads (2 threads per output dim).
// =========================================================================
__global__ void __launch_bounds__(256) precompute_kernel(
    const float* __restrict__ tp_w1,
    const float* __restrict__ tp_b1,
    const float* __restrict__ tp_w2,
    const float* __restrict__ tp_b2)
{
    __shared__ float sw[128], sb[128], sbp[128];
    __shared__ int   srank[128];
    __shared__ float pa[128], pc[128];

    const int tid = threadIdx.x;

    if (tid < 128) {
        const float w = tp_w1[tid], b = tp_b1[tid];
        const float bp = (w != 0.0f) ? (-b / w) : INFINITY;
        sw[tid] = w; sb[tid] = b; sbp[tid] = bp;
    }
    __syncthreads();

    if (tid < 128) {
        const float bp = sbp[tid];
        int r = 0;
        #pragma unroll 8
        for (int j = 0; j < 128; j++) {
            const float bj = sbp[j];
            if (bj < bp || (bj == bp && j < tid)) r++;
        }
        srank[tid] = r;
        if (blockIdx.x == 0) g_bp[r] = bp;
    }
    __syncthreads();

    const int s = blockIdx.x;            // segment id 0..128
    const int d = tid & 127;             // output dim
    const int half = tid >> 7;           // j-range half
    float a = 0.0f, c = 0.0f;
    #pragma unroll 8
    for (int jj = 0; jj < 64; jj++) {
        const int j = half * 64 + jj;
        const float wj = sw[j];
        bool active;
        if (wj > 0.0f)      active = (srank[j] < s);
        else if (wj < 0.0f) active = (srank[j] >= s);
        else                active = (sb[j] > 0.0f);
        if (active) {
            const float w2v = __ldg(&tp_w2[j * 128 + d]);
            a += wj * w2v;
            c += sb[j] * w2v;
        }
    }
    if (half) { pa[d] = a; pc[d] = c; }
    __syncthreads();
    if (!half) {
        g_A[s * 128 + d] = a + pa[d];
        g_C[s * 128 + d] = c + pc[d] + tp_b2[d];
    }
}

// =========================================================================
// Kernel 2: temporal attention encoder, online softmax, single pass.
// One warp per (edge, side). Binary searches hoisted (one per lane, all k in
// parallel); node_emb gather software-pipelined (prefetch depth 1).
// =========================================================================
__global__ void __launch_bounds__(256, 4) encode_kernel(
    const int*   __restrict__ edge_index,
    const int*   __restrict__ ets,
    const int*   __restrict__ hnb,
    const int*   __restrict__ hts,
    const int*   __restrict__ hsg,
    const float* __restrict__ nemb,
    const float* __restrict__ semb)
{
    __shared__ float sbp[128];
    if (threadIdx.x < 128) sbp[threadIdx.x] = g_bp[threadIdx.x];
    __syncthreads();

    const int w    = threadIdx.x >> 5;
    const int lane = threadIdx.x & 31;
    const int task = blockIdx.x * 8 + w;     // 2*NB tasks
    const int e    = task >> 1;
    const int side = task & 1;

    const int node = edge_index[side * NB + e];
    const int qt   = ets[e];
    const float qtf = (float)qt;

    const float4* nemb4 = (const float4*)nemb;
    const float4* semb4 = (const float4*)semb;
    const float4* A4 = (const float4*)g_A;
    const float4* C4 = (const float4*)g_C;

    const float4 q4 = __ldg(&nemb4[node * 32 + lane]);

    // ---- per-lane preprocessing: lane k (<20) owns neighbor k ----
    int   nb_l = 0;        // clamped neighbor id
    float dl_l = 0.0f;     // delta
    int   mt_l = 0;        // (seg<<2) | (sign<<1) | valid
    if (lane < KN) {
        const int nb = hnb[node * KN + lane];
        const int ht = hts[node * KN + lane];
        const int sg = hsg[node * KN + lane];
        const float delta = qtf - (float)ht;
        int lo = 0, hi = 128;
        #pragma unroll
        for (int it = 0; it < 7; it++) {
            const int mid = (lo + hi) >> 1;
            if (sbp[mid] < delta) lo = mid + 1; else hi = mid;
        }
        const bool valid = (nb != -1) && (ht < qt);
        nb_l = (nb == -1) ? 0 : nb;
        dl_l = delta;
        mt_l = (lo << 2) | (sg << 1) | (valid ? 1 : 0);
    }

    // ---- pipelined mainloop ----
    int   nb_c = __shfl_sync(0xffffffffu, nb_l, 0);
    int   mt_c = __shfl_sync(0xffffffffu, mt_l, 0);
    float dl_c = __shfl_sync(0xffffffffu, dl_l, 0);
    float4 em  = __ldg(&nemb4[nb_c * 32 + lane]);

    const float rsH = 0.08838834764831845f;   // 1/sqrt(128)
    float m = -INFINITY;
    float ssum = 0.0f;
    float4 acc = make_float4(0.f, 0.f, 0.f, 0.f);

    #pragma unroll 2
    for (int k = 0; k < KN; k++) {
        // prefetch next neighbor embedding (long-latency L2 gather)
        float4 emn;
        int nb_n = 0, mt_n = 0; float dl_n = 0.0f;
        if (k < KN - 1) {
            nb_n = __shfl_sync(0xffffffffu, nb_l, k + 1);
            mt_n = __shfl_sync(0xffffffffu, mt_l, k + 1);
            dl_n = __shfl_sync(0xffffffffu, dl_l, k + 1);
            emn  = __ldg(&nemb4[nb_n * 32 + lane]);
        }

        // process current k
        const int   seg   = mt_c >> 2;
        const int   sg    = (mt_c >> 1) & 1;
        const bool  valid = mt_c & 1;
        const float delta = dl_c;

        const float4 s4 = __ldg(&semb4[sg * 32 + lane]);
        const float4 a4 = A4[seg * 32 + lane];
        const float4 c4 = C4[seg * 32 + lane];

        const float kx = em.x + s4.x + fmaf(a4.x, delta, c4.x);
        const float ky = em.y + s4.y + fmaf(a4.y, delta, c4.y);
        const float kz = em.z + s4.z + fmaf(a4.z, delta, c4.z);
        const float kw = em.w + s4.w + fmaf(a4.w, delta, c4.w);

        float dp = kx * q4.x + ky * q4.y + kz * q4.z + kw * q4.w;
        #pragma unroll
        for (int off = 16; off > 0; off >>= 1)
            dp += __shfl_xor_sync(0xffffffffu, dp, off);

        const float sc = valid ? dp * rsH : NEGV;

        // online softmax update
        const float mn = fmaxf(m, sc);
        const float f  = __expf(m - mn);    // 0 when m == -inf
        const float we = __expf(sc - mn);
        ssum = ssum * f + we;
        acc.x = fmaf(acc.x, f, we * kx);
        acc.y = fmaf(acc.y, f, we * ky);
        acc.z = fmaf(acc.z, f, we * kz);
        acc.w = fmaf(acc.w, f, we * kw);
        m = mn;

        // rotate pipeline
        if (k < KN - 1) { em = emn; nb_c = nb_n; mt_c = mt_n; dl_c = dl_n; }
    }

    const float inv = 1.0f / ssum;
    acc.x *= inv; acc.y *= inv; acc.z *= inv; acc.w *= inv;
    ((float4*)g_z)[(unsigned)(side * NB + e) * 32 + lane] = acc;
}

// =========================================================================
// Kernel 3: fused final MLP. logits = relu(feat @ W1 + b1) @ w2 + b2
// feat = [zu, zv, |zu-zv|, zu*zv]  => M=65536, N=128, K=512 GEMM + epilogue.
// 128x128 tile / block, 256 threads, 8x8 microtile, packed f32x2 FMA.
// Double-buffered smem (16-wide k chunks), reg-staged prefetch, 1 sync/chunk.
// =========================================================================
__device__ __forceinline__ unsigned long long ffma2(unsigned long long a,
                                                    unsigned long long b,
                                                    unsigned long long c)
{
    unsigned long long d;
    asm("fma.rn.f32x2 %0, %1, %2, %3;" : "=l"(d) : "l"(a), "l"(b), "l"(c));
    return d;
}
__device__ __forceinline__ unsigned long long pack2(float x, float y)
{
    unsigned long long r;
    asm("mov.b64 %0, {%1, %2};" : "=l"(r) : "f"(x), "f"(y));
    return r;
}
__device__ __forceinline__ float2 unpack2(unsigned long long v)
{
    float2 r;
    asm("mov.b64 {%0, %1}, %2;" : "=f"(r.x), "=f"(r.y) : "l"(v));
    return r;
}

__global__ void __launch_bounds__(256, 2) mlp_kernel(
    const float* __restrict__ w1,   // [512,128] row-major [in,out]
    const float* __restrict__ b1,   // [128]
    const float* __restrict__ w2,   // [128]
    const float* __restrict__ b2,   // [1]
    float*       __restrict__ out)  // [NB]
{
    __shared__ float sF[2][128][17];  // feat tile chunk (pad 17: conflict-free)
    __shared__ float sW[2][16][128];  // W1 chunk
    __shared__ float slog[128];

    const int tid = threadIdx.x;
    const int tx = tid & 15;        // n-group
    const int ty = tid >> 4;        // m-group
    const int e0 = blockIdx.x * 128;

    if (tid < 128) slog[tid] = 0.0f;

    unsigned long long acc2[8][4];
    #pragma unroll
    for (int mi = 0; mi < 8; mi++)
        #pragma unroll
        for (int nj = 0; nj < 4; nj++)
            acc2[mi][nj] = 0ULL;

    // staging maps
    const int fi  = tid & 15;       // feat col within chunk
    const int fm0 = tid >> 4;       // feat row base (m = fm0 + 16r)
    const int wn  = tid & 127;      // weight col
    const int wi0 = tid >> 7;       // weight row base (i = wi0 + 2r)

    // step s = ii*4 + region; chunk k0 = region*128 + ii*16
    // ---- prologue: stage step 0 (ii=0, region=0 => zu cols 0..15) ----
    {
        #pragma unroll
        for (int r = 0; r < 8; r++) {
            const int mm = fm0 + 16 * r;
            sF[0][mm][fi] = g_z[(unsigned)(e0 + mm) * 128 + fi];
        }
        #pragma unroll
        for (int r = 0; r < 8; r++) {
            const int i = wi0 + 2 * r;
            sW[0][i][wn] = w1[i * 128 + wn];
        }
    }
    __syncthreads();

    for (int step = 0; step < 32; step++) {
        const int buf = step & 1;

        // ---- load next chunk to registers (overlaps with compute) ----
        float fv[8], wv[8];
        if (step < 31) {
            const int ns = step + 1;
            const int region = ns & 3;
            const int ii0 = (ns >> 2) * 16;
            const int k0 = region * 128 + ii0;
            #pragma unroll
            for (int r = 0; r < 8; r++) {
                const int mm = fm0 + 16 * r;
                const int col = ii0 + fi;
                float v;
                if (region == 0) {
                    v = g_z[(unsigned)(e0 + mm) * 128 + col];
                } else if (region == 1) {
                    v = g_z[(unsigned)(NB + e0 + mm) * 128 + col];
                } else {
                    const float a  = g_z[(unsigned)(e0 + mm) * 128 + col];
                    const float bv = g_z[(unsigned)(NB + e0 + mm) * 128 + col];
                    v = (region == 2) ? fabsf(a - bv) : a * bv;
                }
                fv[r] = v;
            }
            #pragma unroll
            for (int r = 0; r < 8; r++) {
                const int i = wi0 + 2 * r;
                wv[r] = w1[(k0 + i) * 128 + wn];
            }
        }

        // ---- compute current chunk ----
        #pragma unroll
        for (int i = 0; i < 16; i++) {
            unsigned long long av[8];
            #pragma unroll
            for (int mi = 0; mi < 8; mi++) {
                const float a = sF[buf][ty * 8 + mi][i];
                av[mi] = pack2(a, a);
            }
            const float4 bA = *((const float4*)&sW[buf][i][tx * 8]);
            const float4 bB = *((const float4*)&sW[buf][i][tx * 8 + 4]);
            unsigned long long bv4[4];
            bv4[0] = pack2(bA.x, bA.y);
            bv4[1] = pack2(bA.z, bA.w);
            bv4[2] = pack2(bB.x, bB.y);
            bv4[3] = pack2(bB.z, bB.w);
            #pragma unroll
            for (int mi = 0; mi < 8; mi++)
                #pragma unroll
                for (int nj = 0; nj < 4; nj++)
                    acc2[mi][nj] = ffma2(av[mi], bv4[nj], acc2[mi][nj]);
        }

        // ---- store staged regs into the other buffer ----
        if (step < 31) {
            const int nb = 1 - buf;
            #pragma unroll
            for (int r = 0; r < 8; r++) {
                const int mm = fm0 + 16 * r;
                sF[nb][mm][fi] = fv[r];
            }
            #pragma unroll
            for (int r = 0; r < 8; r++) {
                const int i = wi0 + 2 * r;
                sW[nb][i][wn] = wv[r];
            }
        }
        __syncthreads();
    }

    // epilogue: hid = relu(acc + b1); partial logit = hid . w2
    float b1v[8], w2v[8];
    #pragma unroll
    for (int u = 0; u < 8; u++) {
        b1v[u] = b1[tx * 8 + u];
        w2v[u] = w2[tx * 8 + u];
    }
    #pragma unroll
    for (int mi = 0; mi < 8; mi++) {
        float p = 0.0f;
        #pragma unroll
        for (int nj = 0; nj < 4; nj++) {
            const float2 v = unpack2(acc2[mi][nj]);
            const float h0 = fmaxf(v.x + b1v[2 * nj],     0.0f);
            const float h1 = fmaxf(v.y + b1v[2 * nj + 1], 0.0f);
            p += h0 * w2v[2 * nj] + h1 * w2v[2 * nj + 1];
        }
        atomicAdd(&slog[ty * 8 + mi], p);
    }
    __syncthreads();
    if (tid < 128) out[e0 + tid] = slog[tid] + b2[0];
}

// =========================================================================
extern "C" void kernel_launch(void* const* d_in, const int* in_sizes, int n_in,
                              void* d_out, int out_size)
{
    const int*   edge_index = (const int*)  d_in[0];
    const int*   ets        = (const int*)  d_in[1];
    const int*   hnb        = (const int*)  d_in[2];
    const int*   hts        = (const int*)  d_in[3];
    const int*   hsg        = (const int*)  d_in[4];
    const float* nemb       = (const float*)d_in[5];
    const float* semb       = (const float*)d_in[6];
    const float* tp_w1      = (const float*)d_in[7];
    const float* tp_b1      = (const float*)d_in[8];
    const float* tp_w2      = (const float*)d_in[9];
    const float* tp_b2      = (const float*)d_in[10];
    const float* em_w1      = (const float*)d_in[11];
    const float* em_b1      = (const float*)d_in[12];
    const float* em_w2      = (const float*)d_in[13];
    const float* em_b2      = (const float*)d_in[14];
    float* out = (float*)d_out;

    precompute_kernel<<<129, 256>>>(tp_w1, tp_b1, tp_w2, tp_b2);
    encode_kernel<<<(2 * NB) / 8, 256>>>(edge_index, ets, hnb, hts, hsg, nemb, semb);
    mlp_kernel<<<NB / 128, 256>>>(em_w1, em_b1, em_w2, em_b2, out);
}

// round 4
// speedup vs baseline: 1.9658x; 1.0870x over previous
#include <cuda_runtime.h>
#include <math.h>

#define H 128
#define KN 20
#define NB 65536          // batch B
#define NEGV (-1e9f)

// ---------------- device scratch (no allocations allowed) ----------------
__device__ float g_A[129 * 128];          // segment slope rows
__device__ float g_C[129 * 128];          // segment intercept rows (includes tp_b2)
__device__ float g_bp[128];               // sorted breakpoints
__device__ float g_z[2u * NB * 128];      // zu | zv  (67 MB)

// =========================================================================
// Kernel 1: piecewise-linear decomposition of the time-encoder MLP.
// 129 blocks (one per segment) x 512 threads (4 j-quarters per output dim).
// =========================================================================
__global__ void __launch_bounds__(512) precompute_kernel(
    const float* __restrict__ tp_w1,
    const float* __restrict__ tp_b1,
    const float* __restrict__ tp_w2,
    const float* __restrict__ tp_b2)
{
    __shared__ float sw[128], sb[128], sbp[128];
    __shared__ int   srank[128];
    __shared__ float pa[3][128], pc[3][128];

    const int tid = threadIdx.x;

    if (tid < 128) {
        const float w = tp_w1[tid], b = tp_b1[tid];
        const float bp = (w != 0.0f) ? (-b / w) : INFINITY;
        sw[tid] = w; sb[tid] = b; sbp[tid] = bp;
    }
    __syncthreads();

    if (tid < 128) {
        const float bp = sbp[tid];
        int r = 0;
        #pragma unroll 8
        for (int j = 0; j < 128; j++) {
            const float bj = sbp[j];
            if (bj < bp || (bj == bp && j < tid)) r++;
        }
        srank[tid] = r;
        if (blockIdx.x == 0) g_bp[r] = bp;
    }
    __syncthreads();

    const int s = blockIdx.x;            // segment id 0..128
    const int d = tid & 127;             // output dim
    const int q = tid >> 7;              // j-quarter
    float a = 0.0f, c = 0.0f;
    #pragma unroll 8
    for (int jj = 0; jj < 32; jj++) {
        const int j = q * 32 + jj;
        const float wj = sw[j];
        bool active;
        if (wj > 0.0f)      active = (srank[j] < s);
        else if (wj < 0.0f) active = (srank[j] >= s);
        else                active = (sb[j] > 0.0f);
        if (active) {
            const float w2v = __ldg(&tp_w2[j * 128 + d]);
            a = fmaf(wj, w2v, a);
            c = fmaf(sb[j], w2v, c);
        }
    }
    if (q) { pa[q - 1][d] = a; pc[q - 1][d] = c; }
    __syncthreads();
    if (q == 0) {
        g_A[s * 128 + d] = a + pa[0][d] + pa[1][d] + pa[2][d];
        g_C[s * 128 + d] = c + pc[0][d] + pc[1][d] + pc[2][d] + tp_b2[d];
    }
}

// =========================================================================
// Kernel 2: temporal attention encoder, online softmax, unroll-2 pairs.
// One warp per (edge, side). Per-lane meta packed to one word; sign rows in
// registers; pair (k+2,k+3) gather prefetched during pair (k,k+1).
// =========================================================================
__global__ void __launch_bounds__(256) encode_kernel(
    const int*   __restrict__ edge_index,
    const int*   __restrict__ ets,
    const int*   __restrict__ hnb,
    const int*   __restrict__ hts,
    const int*   __restrict__ hsg,
    const float* __restrict__ nemb,
    const float* __restrict__ semb)
{
    __shared__ float sbp[128];
    if (threadIdx.x < 128) sbp[threadIdx.x] = g_bp[threadIdx.x];
    __syncthreads();

    const int w    = threadIdx.x >> 5;
    const int lane = threadIdx.x & 31;
    const int task = blockIdx.x * 8 + w;     // 2*NB tasks
    const int e    = task >> 1;
    const int side = task & 1;

    const int node = edge_index[side * NB + e];
    const int qt   = ets[e];
    const float qtf = (float)qt;

    const float4* nemb4 = (const float4*)nemb;
    const float4* A4 = (const float4*)g_A;
    const float4* C4 = (const float4*)g_C;

    const float4 q4 = __ldg(&nemb4[node * 32 + lane]);
    const float4 s0 = __ldg(&((const float4*)semb)[lane]);
    const float4 s1 = __ldg(&((const float4*)semb)[32 + lane]);

    // ---- per-lane meta: lane k owns neighbor k ----
    // packed: nb(17b) | seg(8b)<<17 | sg<<25 | valid<<26
    unsigned mt_l = 0;
    float    dl_l = 0.0f;
    if (lane < KN) {
        const int nb = hnb[node * KN + lane];
        const int ht = hts[node * KN + lane];
        const int sg = hsg[node * KN + lane];
        const float delta = qtf - (float)ht;
        int lo = 0, hi = 128;
        #pragma unroll
        for (int it = 0; it < 7; it++) {
            const int mid = (lo + hi) >> 1;
            if (sbp[mid] < delta) lo = mid + 1; else hi = mid;
        }
        const bool valid = (nb != -1) && (ht < qt);
        const unsigned nbc = (nb == -1) ? 0u : (unsigned)nb;
        mt_l = nbc | ((unsigned)lo << 17) | ((unsigned)sg << 25)
                   | (valid ? (1u << 26) : 0u);
        dl_l = delta;
    }

    // ---- prologue: pair 0 ----
    unsigned mt0 = __shfl_sync(0xffffffffu, mt_l, 0);
    unsigned mt1 = __shfl_sync(0xffffffffu, mt_l, 1);
    float    dl0 = __shfl_sync(0xffffffffu, dl_l, 0);
    float    dl1 = __shfl_sync(0xffffffffu, dl_l, 1);
    float4 em0 = __ldg(&nemb4[(mt0 & 0x1FFFFu) * 32 + lane]);
    float4 em1 = __ldg(&nemb4[(mt1 & 0x1FFFFu) * 32 + lane]);

    const float rsH = 0.08838834764831845f;   // 1/sqrt(128)
    float m = -INFINITY;
    float ssum = 0.0f;
    float4 acc = make_float4(0.f, 0.f, 0.f, 0.f);

    #pragma unroll
    for (int k = 0; k < KN; k += 2) {
        // prefetch next pair's gathers
        unsigned mtA = 0, mtB = 0;
        float dlA = 0.f, dlB = 0.f;
        float4 emA, emB;
        if (k + 2 < KN) {
            mtA = __shfl_sync(0xffffffffu, mt_l, k + 2);
            mtB = __shfl_sync(0xffffffffu, mt_l, k + 3);
            dlA = __shfl_sync(0xffffffffu, dl_l, k + 2);
            dlB = __shfl_sync(0xffffffffu, dl_l, k + 3);
            emA = __ldg(&nemb4[(mtA & 0x1FFFFu) * 32 + lane]);
            emB = __ldg(&nemb4[(mtB & 0x1FFFFu) * 32 + lane]);
        }

        // ---- process pair (two independent chains) ----
        const int seg0 = (mt0 >> 17) & 0xFF;
        const int seg1 = (mt1 >> 17) & 0xFF;
        const float4 sg0 = (mt0 & (1u << 25)) ? s1 : s0;
        const float4 sg1 = (mt1 & (1u << 25)) ? s1 : s0;
        const float4 a40 = A4[seg0 * 32 + lane];
        const float4 c40 = C4[seg0 * 32 + lane];
        const float4 a41 = A4[seg1 * 32 + lane];
        const float4 c41 = C4[seg1 * 32 + lane];

        const float k0x = em0.x + sg0.x + fmaf(a40.x, dl0, c40.x);
        const float k0y = em0.y + sg0.y + fmaf(a40.y, dl0, c40.y);
        const float k0z = em0.z + sg0.z + fmaf(a40.z, dl0, c40.z);
        const float k0w = em0.w + sg0.w + fmaf(a40.w, dl0, c40.w);
        const float k1x = em1.x + sg1.x + fmaf(a41.x, dl1, c41.x);
        const float k1y = em1.y + sg1.y + fmaf(a41.y, dl1, c41.y);
        const float k1z = em1.z + sg1.z + fmaf(a41.z, dl1, c41.z);
        const float k1w = em1.w + sg1.w + fmaf(a41.w, dl1, c41.w);

        float dp0 = fmaf(k0x, q4.x, fmaf(k0y, q4.y, fmaf(k0z, q4.z, k0w * q4.w)));
        float dp1 = fmaf(k1x, q4.x, fmaf(k1y, q4.y, fmaf(k1z, q4.z, k1w * q4.w)));
        #pragma unroll
        for (int off = 16; off > 0; off >>= 1) {
            dp0 += __shfl_xor_sync(0xffffffffu, dp0, off);
            dp1 += __shfl_xor_sync(0xffffffffu, dp1, off);
        }

        const float sc0 = (mt0 & (1u << 26)) ? dp0 * rsH : NEGV;
        const float sc1 = (mt1 & (1u << 26)) ? dp1 * rsH : NEGV;

        // pair online-softmax update
        const float mn = fmaxf(m, fmaxf(sc0, sc1));
        const float f  = __expf(m - mn);      // 0 when m == -inf
        const float w0 = __expf(sc0 - mn);
        const float w1 = __expf(sc1 - mn);
        ssum = fmaf(ssum, f, w0 + w1);
        acc.x = fmaf(w1, k1x, fmaf(w0, k0x, acc.x * f));
        acc.y = fmaf(w1, k1y, fmaf(w0, k0y, acc.y * f));
        acc.z = fmaf(w1, k1z, fmaf(w0, k0z, acc.z * f));
        acc.w = fmaf(w1, k1w, fmaf(w0, k0w, acc.w * f));
        m = mn;

        // rotate pipeline
        if (k + 2 < KN) {
            mt0 = mtA; dl0 = dlA; em0 = emA;
            mt1 = mtB; dl1 = dlB; em1 = emB;
        }
    }

    const float inv = 1.0f / ssum;
    acc.x *= inv; acc.y *= inv; acc.z *= inv; acc.w *= inv;
    ((float4*)g_z)[(unsigned)(side * NB + e) * 32 + lane] = acc;
}

// =========================================================================
// Kernel 3: fused final MLP (unchanged from round 3).
// =========================================================================
__device__ __forceinline__ unsigned long long ffma2(unsigned long long a,
                                                    unsigned long long b,
                                                    unsigned long long c)
{
    unsigned long long d;
    asm("fma.rn.f32x2 %0, %1, %2, %3;" : "=l"(d) : "l"(a), "l"(b), "l"(c));
    return d;
}
__device__ __forceinline__ unsigned long long pack2(float x, float y)
{
    unsigned long long r;
    asm("mov.b64 %0, {%1, %2};" : "=l"(r) : "f"(x), "f"(y));
    return r;
}
__device__ __forceinline__ float2 unpack2(unsigned long long v)
{
    float2 r;
    asm("mov.b64 {%0, %1}, %2;" : "=f"(r.x), "=f"(r.y) : "l"(v));
    return r;
}

__global__ void __launch_bounds__(256, 2) mlp_kernel(
    const float* __restrict__ w1,   // [512,128] row-major [in,out]
    const float* __restrict__ b1,   // [128]
    const float* __restrict__ w2,   // [128]
    const float* __restrict__ b2,   // [1]
    float*       __restrict__ out)  // [NB]
{
    __shared__ float sF[2][128][17];  // feat tile chunk (pad 17)
    __shared__ float sW[2][16][128];  // W1 chunk
    __shared__ float slog[128];

    const int tid = threadIdx.x;
    const int tx = tid & 15;
    const int ty = tid >> 4;
    const int e0 = blockIdx.x * 128;

    if (tid < 128) slog[tid] = 0.0f;

    unsigned long long acc2[8][4];
    #pragma unroll
    for (int mi = 0; mi < 8; mi++)
        #pragma unroll
        for (int nj = 0; nj < 4; nj++)
            acc2[mi][nj] = 0ULL;

    const int fi  = tid & 15;
    const int fm0 = tid >> 4;
    const int wn  = tid & 127;
    const int wi0 = tid >> 7;

    {
        #pragma unroll
        for (int r = 0; r < 8; r++) {
            const int mm = fm0 + 16 * r;
            sF[0][mm][fi] = g_z[(unsigned)(e0 + mm) * 128 + fi];
        }
        #pragma unroll
        for (int r = 0; r < 8; r++) {
            const int i = wi0 + 2 * r;
            sW[0][i][wn] = w1[i * 128 + wn];
        }
    }
    __syncthreads();

    for (int step = 0; step < 32; step++) {
        const int buf = step & 1;

        float fv[8], wv[8];
        if (step < 31) {
            const int ns = step + 1;
            const int region = ns & 3;
            const int ii0 = (ns >> 2) * 16;
            const int k0 = region * 128 + ii0;
            #pragma unroll
            for (int r = 0; r < 8; r++) {
                const int mm = fm0 + 16 * r;
                const int col = ii0 + fi;
                float v;
                if (region == 0) {
                    v = g_z[(unsigned)(e0 + mm) * 128 + col];
                } else if (region == 1) {
                    v = g_z[(unsigned)(NB + e0 + mm) * 128 + col];
                } else {
                    const float a  = g_z[(unsigned)(e0 + mm) * 128 + col];
                    const float bv = g_z[(unsigned)(NB + e0 + mm) * 128 + col];
                    v = (region == 2) ? fabsf(a - bv) : a * bv;
                }
                fv[r] = v;
            }
            #pragma unroll
            for (int r = 0; r < 8; r++) {
                const int i = wi0 + 2 * r;
                wv[r] = w1[(k0 + i) * 128 + wn];
            }
        }

        #pragma unroll
        for (int i = 0; i < 16; i++) {
            unsigned long long av[8];
            #pragma unroll
            for (int mi = 0; mi < 8; mi++) {
                const float a = sF[buf][ty * 8 + mi][i];
                av[mi] = pack2(a, a);
            }
            const float4 bA = *((const float4*)&sW[buf][i][tx * 8]);
            const float4 bB = *((const float4*)&sW[buf][i][tx * 8 + 4]);
            unsigned long long bv4[4];
            bv4[0] = pack2(bA.x, bA.y);
            bv4[1] = pack2(bA.z, bA.w);
            bv4[2] = pack2(bB.x, bB.y);
            bv4[3] = pack2(bB.z, bB.w);
            #pragma unroll
            for (int mi = 0; mi < 8; mi++)
                #pragma unroll
                for (int nj = 0; nj < 4; nj++)
                    acc2[mi][nj] = ffma2(av[mi], bv4[nj], acc2[mi][nj]);
        }

        if (step < 31) {
            const int nb = 1 - buf;
            #pragma unroll
            for (int r = 0; r < 8; r++) {
                const int mm = fm0 + 16 * r;
                sF[nb][mm][fi] = fv[r];
            }
            #pragma unroll
            for (int r = 0; r < 8; r++) {
                const int i = wi0 + 2 * r;
                sW[nb][i][wn] = wv[r];
            }
        }
        __syncthreads();
    }

    float b1v[8], w2v[8];
    #pragma unroll
    for (int u = 0; u < 8; u++) {
        b1v[u] = b1[tx * 8 + u];
        w2v[u] = w2[tx * 8 + u];
    }
    #pragma unroll
    for (int mi = 0; mi < 8; mi++) {
        float p = 0.0f;
        #pragma unroll
        for (int nj = 0; nj < 4; nj++) {
            const float2 v = unpack2(acc2[mi][nj]);
            const float h0 = fmaxf(v.x + b1v[2 * nj],     0.0f);
            const float h1 = fmaxf(v.y + b1v[2 * nj + 1], 0.0f);
            p += h0 * w2v[2 * nj] + h1 * w2v[2 * nj + 1];
        }
        atomicAdd(&slog[ty * 8 + mi], p);
    }
    __syncthreads();
    if (tid < 128) out[e0 + tid] = slog[tid] + b2[0];
}

// =========================================================================
extern "C" void kernel_launch(void* const* d_in, const int* in_sizes, int n_in,
                              void* d_out, int out_size)
{
    const int*   edge_index = (const int*)  d_in[0];
    const int*   ets        = (const int*)  d_in[1];
    const int*   hnb        = (const int*)  d_in[2];
    const int*   hts        = (const int*)  d_in[3];
    const int*   hsg        = (const int*)  d_in[4];
    const float* nemb       = (const float*)d_in[5];
    const float* semb       = (const float*)d_in[6];
    const float* tp_w1      = (const float*)d_in[7];
    const float* tp_b1      = (const float*)d_in[8];
    const float* tp_w2      = (const float*)d_in[9];
    const float* tp_b2      = (const float*)d_in[10];
    const float* em_w1      = (const float*)d_in[11];
    const float* em_b1      = (const float*)d_in[12];
    const float* em_w2      = (const float*)d_in[13];
    const float* em_b2      = (const float*)d_in[14];
    float* out = (float*)d_out;

    precompute_kernel<<<129, 512>>>(tp_w1, tp_b1, tp_w2, tp_b2);
    encode_kernel<<<(2 * NB) / 8, 256>>>(edge_index, ets, hnb, hts, hsg, nemb, semb);
    mlp_kernel<<<NB / 128, 256>>>(em_w1, em_b1, em_w2, em_b2, out);
}

// round 6
// speedup vs baseline: 2.5349x; 1.2895x over previous
#include <cuda_runtime.h>
#include <cuda_bf16.h>
#include <math.h>
#include <stdint.h>

#define H 128
#define KN 20
#define NB 65536
#define NEGV (-1e9f)

// ---------------- device scratch ----------------
__device__ float g_A[129 * 128];
__device__ float g_C[129 * 128];
__device__ float g_bp[128];
__device__ float g_z[2u * NB * 128];                 // zu | zv
__device__ unsigned short g_Whi[128 * 512];          // W1^T hi (bf16 bits) [n][k]
__device__ unsigned short g_Wlo[128 * 512];          // W1^T lo

// =========================================================================
// Kernel 1: piecewise-linear decomposition of the time-encoder MLP.
// =========================================================================
__global__ void __launch_bounds__(512) precompute_kernel(
    const float* __restrict__ tp_w1, const float* __restrict__ tp_b1,
    const float* __restrict__ tp_w2, const float* __restrict__ tp_b2)
{
    __shared__ float sw[128], sb[128], sbp[128];
    __shared__ int   srank[128];
    __shared__ float pa[3][128], pc[3][128];

    const int tid = threadIdx.x;
    if (tid < 128) {
        const float w = tp_w1[tid], b = tp_b1[tid];
        const float bp = (w != 0.0f) ? (-b / w) : INFINITY;
        sw[tid] = w; sb[tid] = b; sbp[tid] = bp;
    }
    __syncthreads();
    if (tid < 128) {
        const float bp = sbp[tid];
        int r = 0;
        #pragma unroll 8
        for (int j = 0; j < 128; j++) {
            const float bj = sbp[j];
            if (bj < bp || (bj == bp && j < tid)) r++;
        }
        srank[tid] = r;
        if (blockIdx.x == 0) g_bp[r] = bp;
    }
    __syncthreads();

    const int s = blockIdx.x;
    const int d = tid & 127;
    const int q = tid >> 7;
    float a = 0.0f, c = 0.0f;
    #pragma unroll 8
    for (int jj = 0; jj < 32; jj++) {
        const int j = q * 32 + jj;
        const float wj = sw[j];
        bool active;
        if (wj > 0.0f)      active = (srank[j] < s);
        else if (wj < 0.0f) active = (srank[j] >= s);
        else                active = (sb[j] > 0.0f);
        if (active) {
            const float w2v = __ldg(&tp_w2[j * 128 + d]);
            a = fmaf(wj, w2v, a);
            c = fmaf(sb[j], w2v, c);
        }
    }
    if (q) { pa[q - 1][d] = a; pc[q - 1][d] = c; }
    __syncthreads();
    if (q == 0) {
        g_A[s * 128 + d] = a + pa[0][d] + pa[1][d] + pa[2][d];
        g_C[s * 128 + d] = c + pc[0][d] + pc[1][d] + pc[2][d] + tp_b2[d];
    }
}

// =========================================================================
// Kernel 1b: transpose + bf16 hi/lo split of W1 [512,128] -> Wt [128,512].
// =========================================================================
__global__ void __launch_bounds__(256) wsplit_kernel(const float* __restrict__ w1)
{
    __shared__ float s[32][33];
    const int bx = blockIdx.x & 15;   // k-tile (512/32)
    const int by = blockIdx.x >> 4;   // n-tile (128/32)
    const int c = threadIdx.x & 31;
    const int r8 = threadIdx.x >> 5;
    #pragma unroll
    for (int p = 0; p < 4; p++) {
        const int r = r8 + p * 8;
        s[r][c] = w1[(bx * 32 + r) * 128 + by * 32 + c];
    }
    __syncthreads();
    #pragma unroll
    for (int p = 0; p < 4; p++) {
        const int r = r8 + p * 8;
        const int n = by * 32 + r;
        const float v = s[c][r];
        const __nv_bfloat16 hb = __float2bfloat16_rn(v);
        const float rres = v - __bfloat162float(hb);
        const __nv_bfloat16 lb = __float2bfloat16_rn(rres);
        g_Whi[n * 512 + bx * 32 + c] = __bfloat16_as_ushort(hb);
        g_Wlo[n * 512 + bx * 32 + c] = __bfloat16_as_ushort(lb);
    }
}

// =========================================================================
// Kernel 2: temporal attention encoder, online softmax, quad pipeline.
// =========================================================================
__global__ void __launch_bounds__(256) encode_kernel(
    const int*   __restrict__ edge_index,
    const int*   __restrict__ ets,
    const int*   __restrict__ hnb,
    const int*   __restrict__ hts,
    const int*   __restrict__ hsg,
    const float* __restrict__ nemb,
    const float* __restrict__ semb)
{
    __shared__ float sbp[128];
    if (threadIdx.x < 128) sbp[threadIdx.x] = g_bp[threadIdx.x];
    __syncthreads();

    const int w    = threadIdx.x >> 5;
    const int lane = threadIdx.x & 31;
    const int task = blockIdx.x * 8 + w;
    const int e    = task >> 1;
    const int side = task & 1;

    const int node = edge_index[side * NB + e];
    const int qt   = ets[e];
    const float qtf = (float)qt;

    const float4* nemb4 = (const float4*)nemb;
    const float4* A4 = (const float4*)g_A;
    const float4* C4 = (const float4*)g_C;

    const float4 q4 = __ldg(&nemb4[node * 32 + lane]);
    const float4 s0 = __ldg(&((const float4*)semb)[lane]);
    const float4 s1 = __ldg(&((const float4*)semb)[32 + lane]);

    // per-lane meta: nb(17b) | seg(8b)<<17 | sg<<25 | valid<<26
    unsigned mt_l = 0;
    float    dl_l = 0.0f;
    if (lane < KN) {
        const int nb = hnb[node * KN + lane];
        const int ht = hts[node * KN + lane];
        const int sg = hsg[node * KN + lane];
        const float delta = qtf - (float)ht;
        int lo = 0, hi = 128;
        #pragma unroll
        for (int it = 0; it < 7; it++) {
            const int mid = (lo + hi) >> 1;
            if (sbp[mid] < delta) lo = mid + 1; else hi = mid;
        }
        const bool valid = (nb != -1) && (ht < qt);
        const unsigned nbc = (nb == -1) ? 0u : (unsigned)nb;
        mt_l = nbc | ((unsigned)lo << 17) | ((unsigned)sg << 25) | (valid ? (1u << 26) : 0u);
        dl_l = delta;
    }

    unsigned mt[4]; float dl[4]; float4 em[4];
    #pragma unroll
    for (int i = 0; i < 4; i++) {
        mt[i] = __shfl_sync(0xffffffffu, mt_l, i);
        dl[i] = __shfl_sync(0xffffffffu, dl_l, i);
        em[i] = __ldg(&nemb4[(mt[i] & 0x1FFFFu) * 32 + lane]);
    }

    const float rsH = 0.08838834764831845f;
    float m = -INFINITY;
    float ssum = 0.0f;
    float4 acc = make_float4(0.f, 0.f, 0.f, 0.f);

    #pragma unroll
    for (int g = 0; g < 5; g++) {
        unsigned mtn[4]; float dln[4]; float4 emn[4];
        if (g < 4) {
            #pragma unroll
            for (int i = 0; i < 4; i++) {
                const int k = (g + 1) * 4 + i;
                mtn[i] = __shfl_sync(0xffffffffu, mt_l, k);
                dln[i] = __shfl_sync(0xffffffffu, dl_l, k);
                emn[i] = __ldg(&nemb4[(mtn[i] & 0x1FFFFu) * 32 + lane]);
            }
        }

        float4 kv[4]; float dp[4];
        #pragma unroll
        for (int i = 0; i < 4; i++) {
            const int seg = (mt[i] >> 17) & 0xFF;
            const float4 sg4 = (mt[i] & (1u << 25)) ? s1 : s0;
            const float4 a4 = A4[seg * 32 + lane];
            const float4 c4 = C4[seg * 32 + lane];
            kv[i].x = em[i].x + sg4.x + fmaf(a4.x, dl[i], c4.x);
            kv[i].y = em[i].y + sg4.y + fmaf(a4.y, dl[i], c4.y);
            kv[i].z = em[i].z + sg4.z + fmaf(a4.z, dl[i], c4.z);
            kv[i].w = em[i].w + sg4.w + fmaf(a4.w, dl[i], c4.w);
            dp[i] = fmaf(kv[i].x, q4.x, fmaf(kv[i].y, q4.y,
                    fmaf(kv[i].z, q4.z, kv[i].w * q4.w)));
        }

        // merged 4-way butterfly reduction
        const float r0 = dp[0] + __shfl_xor_sync(0xffffffffu, dp[0], 16);
        const float r1 = dp[1] + __shfl_xor_sync(0xffffffffu, dp[1], 16);
        const float r2 = dp[2] + __shfl_xor_sync(0xffffffffu, dp[2], 16);
        const float r3 = dp[3] + __shfl_xor_sync(0xffffffffu, dp[3], 16);
        const float m01 = (lane & 16) ? r1 : r0;
        const float m23 = (lane & 16) ? r3 : r2;
        const float q01 = m01 + __shfl_xor_sync(0xffffffffu, m01, 8);
        const float q23 = m23 + __shfl_xor_sync(0xffffffffu, m23, 8);
        float mm = (lane & 8) ? q23 : q01;
        mm += __shfl_xor_sync(0xffffffffu, mm, 4);
        mm += __shfl_xor_sync(0xffffffffu, mm, 2);
        mm += __shfl_xor_sync(0xffffffffu, mm, 1);
        const float t0 = __shfl_sync(0xffffffffu, mm, 0);
        const float t1 = __shfl_sync(0xffffffffu, mm, 16);
        const float t2 = __shfl_sync(0xffffffffu, mm, 8);
        const float t3 = __shfl_sync(0xffffffffu, mm, 24);

        const float sc0 = (mt[0] & (1u << 26)) ? t0 * rsH : NEGV;
        const float sc1 = (mt[1] & (1u << 26)) ? t1 * rsH : NEGV;
        const float sc2 = (mt[2] & (1u << 26)) ? t2 * rsH : NEGV;
        const float sc3 = (mt[3] & (1u << 26)) ? t3 * rsH : NEGV;

        const float mn = fmaxf(m, fmaxf(fmaxf(sc0, sc1), fmaxf(sc2, sc3)));
        const float f  = __expf(m - mn);
        const float w0 = __expf(sc0 - mn);
        const float w1 = __expf(sc1 - mn);
        const float w2 = __expf(sc2 - mn);
        const float w3 = __expf(sc3 - mn);
        ssum = fmaf(ssum, f, w0 + w1 + w2 + w3);
        acc.x = fmaf(w3, kv[3].x, fmaf(w2, kv[2].x, fmaf(w1, kv[1].x, fmaf(w0, kv[0].x, acc.x * f))));
        acc.y = fmaf(w3, kv[3].y, fmaf(w2, kv[2].y, fmaf(w1, kv[1].y, fmaf(w0, kv[0].y, acc.y * f))));
        acc.z = fmaf(w3, kv[3].z, fmaf(w2, kv[2].z, fmaf(w1, kv[1].z, fmaf(w0, kv[0].z, acc.z * f))));
        acc.w = fmaf(w3, kv[3].w, fmaf(w2, kv[2].w, fmaf(w1, kv[1].w, fmaf(w0, kv[0].w, acc.w * f))));
        m = mn;

        if (g < 4) {
            #pragma unroll
            for (int i = 0; i < 4; i++) { mt[i] = mtn[i]; dl[i] = dln[i]; em[i] = emn[i]; }
        }
    }

    const float inv = 1.0f / ssum;
    acc.x *= inv; acc.y *= inv; acc.z *= inv; acc.w *= inv;
    ((float4*)g_z)[(unsigned)(side * NB + e) * 32 + lane] = acc;
}

// =========================================================================
// Kernel 3: split-bf16 mma.sync GEMM MLP.
// Per block: 128 rows x N=128 x K=512 (8 chunks of 64).
// D = Fhi@Whi + Fhi@Wlo + Flo@Whi (fp32 accum). Epilogue: relu+b1, dot w2.
// 256 threads = 8 warps: 4 m-groups x 2 n-groups; warp tile 32(M) x 64(N).
// Fragments loaded manually from padded smem (pitch 144B -> conflict-free).
// =========================================================================
#define MMA_BF16(C, A, B0, B1) \
    asm volatile("mma.sync.aligned.m16n8k16.row.col.f32.bf16.bf16.f32 " \
        "{%0,%1,%2,%3}, {%4,%5,%6,%7}, {%8,%9}, {%0,%1,%2,%3};" \
        : "+f"((C)[0]), "+f"((C)[1]), "+f"((C)[2]), "+f"((C)[3]) \
        : "r"((A)[0]), "r"((A)[1]), "r"((A)[2]), "r"((A)[3]), "r"(B0), "r"(B1))

extern __shared__ char dsm[];
__global__ void __launch_bounds__(256) mlp_mma_kernel(
    const float* __restrict__ b1,
    const float* __restrict__ w2,
    const float* __restrict__ b2,
    float*       __restrict__ out)
{
    __shared__ float slog[128];

    const int tid  = threadIdx.x;
    const int wid  = tid >> 5;
    const int lane = tid & 31;
    const int e0   = blockIdx.x * 128;

    char* sAhi = dsm;
    char* sAlo = dsm + 18432;
    char* sBhi = dsm + 36864;
    char* sBlo = dsm + 55296;

    if (tid < 128) slog[tid] = 0.0f;

    const int wm = wid >> 1;          // m-group 0..3
    const int wn = wid & 1;           // n-group 0..1
    const int g  = lane >> 2;         // 0..7
    const int t2 = (lane & 3) * 2;    // 0,2,4,6

    float acc[2][8][4];
    #pragma unroll
    for (int mt = 0; mt < 2; mt++)
        #pragma unroll
        for (int nt = 0; nt < 8; nt++)
            #pragma unroll
            for (int u = 0; u < 4; u++)
                acc[mt][nt][u] = 0.0f;

    const int f4 = tid & 15;
    const int r0 = tid >> 4;

    for (int chunk = 0; chunk < 8; chunk++) {
        const int region = chunk >> 1;
        const int cb4 = (chunk & 1) * 16;
        __syncthreads();

        // ---- stage A (feat chunk, bf16 hi/lo, pitch 72 bf16) ----
        #pragma unroll
        for (int p = 0; p < 8; p++) {
            const int r = r0 + p * 16;
            float4 v;
            if (region == 0) {
                v = ((const float4*)g_z)[(unsigned)(e0 + r) * 32 + cb4 + f4];
            } else if (region == 1) {
                v = ((const float4*)g_z)[(unsigned)(NB + e0 + r) * 32 + cb4 + f4];
            } else {
                const float4 a = ((const float4*)g_z)[(unsigned)(e0 + r) * 32 + cb4 + f4];
                const float4 b = ((const float4*)g_z)[(unsigned)(NB + e0 + r) * 32 + cb4 + f4];
                if (region == 2) {
                    v.x = fabsf(a.x - b.x); v.y = fabsf(a.y - b.y);
                    v.z = fabsf(a.z - b.z); v.w = fabsf(a.w - b.w);
                } else {
                    v.x = a.x * b.x; v.y = a.y * b.y;
                    v.z = a.z * b.z; v.w = a.w * b.w;
                }
            }
            const __nv_bfloat16 hx = __float2bfloat16_rn(v.x);
            const __nv_bfloat16 hy = __float2bfloat16_rn(v.y);
            const __nv_bfloat16 hz = __float2bfloat16_rn(v.z);
            const __nv_bfloat16 hw = __float2bfloat16_rn(v.w);
            const __nv_bfloat16 lx = __float2bfloat16_rn(v.x - __bfloat162float(hx));
            const __nv_bfloat16 ly = __float2bfloat16_rn(v.y - __bfloat162float(hy));
            const __nv_bfloat16 lz = __float2bfloat16_rn(v.z - __bfloat162float(hz));
            const __nv_bfloat16 lw = __float2bfloat16_rn(v.w - __bfloat162float(hw));
            uint2 hv, lv;
            hv.x = (uint32_t)__bfloat16_as_ushort(hx) | ((uint32_t)__bfloat16_as_ushort(hy) << 16);
            hv.y = (uint32_t)__bfloat16_as_ushort(hz) | ((uint32_t)__bfloat16_as_ushort(hw) << 16);
            lv.x = (uint32_t)__bfloat16_as_ushort(lx) | ((uint32_t)__bfloat16_as_ushort(ly) << 16);
            lv.y = (uint32_t)__bfloat16_as_ushort(lz) | ((uint32_t)__bfloat16_as_ushort(lw) << 16);
            *(uint2*)(sAhi + r * 144 + f4 * 8) = hv;
            *(uint2*)(sAlo + r * 144 + f4 * 8) = lv;
        }
        // ---- stage B (W^T chunk) ----
        {
            const int n = tid >> 1;
            const int hk = tid & 1;
            #pragma unroll
            for (int i = 0; i < 4; i++) {
                const int kk = chunk * 64 + hk * 32 + i * 8;
                const int so = n * 144 + (hk * 32 + i * 8) * 2;
                *(uint4*)(sBhi + so) = *(const uint4*)&g_Whi[n * 512 + kk];
                *(uint4*)(sBlo + so) = *(const uint4*)&g_Wlo[n * 512 + kk];
            }
        }
        __syncthreads();

        #pragma unroll
        for (int ks = 0; ks < 4; ks++) {
            const int cA = (ks * 16 + t2) * 2;
            uint32_t ah[2][4], al[2][4];
            #pragma unroll
            for (int mt = 0; mt < 2; mt++) {
                const int row = wm * 32 + mt * 16 + g;
                ah[mt][0] = *(const uint32_t*)(sAhi + row * 144 + cA);
                ah[mt][1] = *(const uint32_t*)(sAhi + (row + 8) * 144 + cA);
                ah[mt][2] = *(const uint32_t*)(sAhi + row * 144 + cA + 16);
                ah[mt][3] = *(const uint32_t*)(sAhi + (row + 8) * 144 + cA + 16);
                al[mt][0] = *(const uint32_t*)(sAlo + row * 144 + cA);
                al[mt][1] = *(const uint32_t*)(sAlo + (row + 8) * 144 + cA);
                al[mt][2] = *(const uint32_t*)(sAlo + row * 144 + cA + 16);
                al[mt][3] = *(const uint32_t*)(sAlo + (row + 8) * 144 + cA + 16);
            }
            #pragma unroll
            for (int nt = 0; nt < 8; nt++) {
                const int n = wn * 64 + nt * 8 + g;
                const uint32_t bh0 = *(const uint32_t*)(sBhi + n * 144 + cA);
                const uint32_t bh1 = *(const uint32_t*)(sBhi + n * 144 + cA + 16);
                const uint32_t bl0 = *(const uint32_t*)(sBlo + n * 144 + cA);
                const uint32_t bl1 = *(const uint32_t*)(sBlo + n * 144 + cA + 16);
                #pragma unroll
                for (int mt = 0; mt < 2; mt++) {
                    MMA_BF16(acc[mt][nt], ah[mt], bh0, bh1);
                    MMA_BF16(acc[mt][nt], ah[mt], bl0, bl1);
                    MMA_BF16(acc[mt][nt], al[mt], bh0, bh1);
                }
            }
        }
    }
    __syncthreads();

    // ---- epilogue ----
    float b1v[16], w2v[16];
    #pragma unroll
    for (int nt = 0; nt < 8; nt++) {
        const int n = wn * 64 + nt * 8 + t2;
        b1v[nt * 2]     = __ldg(&b1[n]);
        b1v[nt * 2 + 1] = __ldg(&b1[n + 1]);
        w2v[nt * 2]     = __ldg(&w2[n]);
        w2v[nt * 2 + 1] = __ldg(&w2[n + 1]);
    }
    #pragma unroll
    for (int mt = 0; mt < 2; mt++) {
        float p1 = 0.0f, p2 = 0.0f;
        #pragma unroll
        for (int nt = 0; nt < 8; nt++) {
            p1 += fmaxf(acc[mt][nt][0] + b1v[2 * nt],     0.0f) * w2v[2 * nt]
                + fmaxf(acc[mt][nt][1] + b1v[2 * nt + 1], 0.0f) * w2v[2 * nt + 1];
            p2 += fmaxf(acc[mt][nt][2] + b1v[2 * nt],     0.0f) * w2v[2 * nt]
                + fmaxf(acc[mt][nt][3] + b1v[2 * nt + 1], 0.0f) * w2v[2 * nt + 1];
        }
        const int r1 = wm * 32 + mt * 16 + g;
        atomicAdd(&slog[r1], p1);
        atomicAdd(&slog[r1 + 8], p2);
    }
    __syncthreads();
    if (tid < 128) out[e0 + tid] = slog[tid] + b2[0];
}

// =========================================================================
extern "C" void kernel_launch(void* const* d_in, const int* in_sizes, int n_in,
                              void* d_out, int out_size)
{
    const int*   edge_index = (const int*)  d_in[0];
    const int*   ets        = (const int*)  d_in[1];
    const int*   hnb        = (const int*)  d_in[2];
    const int*   hts        = (const int*)  d_in[3];
    const int*   hsg        = (const int*)  d_in[4];
    const float* nemb       = (const float*)d_in[5];
    const float* semb       = (const float*)d_in[6];
    const float* tp_w1      = (const float*)d_in[7];
    const float* tp_b1      = (const float*)d_in[8];
    const float* tp_w2      = (const float*)d_in[9];
    const float* tp_b2      = (const float*)d_in[10];
    const float* em_w1      = (const float*)d_in[11];
    const float* em_b1      = (const float*)d_in[12];
    const float* em_w2      = (const float*)d_in[13];
    const float* em_b2      = (const float*)d_in[14];
    float* out = (float*)d_out;

    cudaFuncSetAttribute(mlp_mma_kernel,
                         cudaFuncAttributeMaxDynamicSharedMemorySize, 73728);

    precompute_kernel<<<129, 512>>>(tp_w1, tp_b1, tp_w2, tp_b2);
    wsplit_kernel<<<64, 256>>>(em_w1);
    encode_kernel<<<(2 * NB) / 8, 256>>>(edge_index, ets, hnb, hts, hsg, nemb, semb);
    mlp_mma_kernel<<<NB / 128, 256, 73728>>>(em_b1, em_w2, em_b2, out);
}

// round 7
// speedup vs baseline: 2.5438x; 1.0035x over previous
#include <cuda_runtime.h>
#include <cuda_bf16.h>
#include <math.h>
#include <stdint.h>

#define H 128
#define KN 20
#define NB 65536
#define NEGV (-1e9f)

// ---------------- device scratch ----------------
__device__ float g_A[129 * 128];
__device__ float g_C[129 * 128];
__device__ float g_bp[128];
__device__ float g_z[2u * NB * 128];                 // zu | zv
__device__ unsigned short g_Whi[128 * 512];          // W1^T hi (bf16 bits) [n][k]
__device__ unsigned short g_Wlo[128 * 512];          // W1^T lo

// =========================================================================
// Kernel 1: piecewise-linear decomposition of the time-encoder MLP.
// =========================================================================
__global__ void __launch_bounds__(512) precompute_kernel(
    const float* __restrict__ tp_w1, const float* __restrict__ tp_b1,
    const float* __restrict__ tp_w2, const float* __restrict__ tp_b2)
{
    __shared__ float sw[128], sb[128], sbp[128];
    __shared__ int   srank[128];
    __shared__ float pa[3][128], pc[3][128];

    const int tid = threadIdx.x;
    if (tid < 128) {
        const float w = tp_w1[tid], b = tp_b1[tid];
        const float bp = (w != 0.0f) ? (-b / w) : INFINITY;
        sw[tid] = w; sb[tid] = b; sbp[tid] = bp;
    }
    __syncthreads();
    if (tid < 128) {
        const float bp = sbp[tid];
        int r = 0;
        #pragma unroll 8
        for (int j = 0; j < 128; j++) {
            const float bj = sbp[j];
            if (bj < bp || (bj == bp && j < tid)) r++;
        }
        srank[tid] = r;
        if (blockIdx.x == 0) g_bp[r] = bp;
    }
    __syncthreads();

    const int s = blockIdx.x;
    const int d = tid & 127;
    const int q = tid >> 7;
    float a = 0.0f, c = 0.0f;
    #pragma unroll 8
    for (int jj = 0; jj < 32; jj++) {
        const int j = q * 32 + jj;
        const float wj = sw[j];
        bool active;
        if (wj > 0.0f)      active = (srank[j] < s);
        else if (wj < 0.0f) active = (srank[j] >= s);
        else                active = (sb[j] > 0.0f);
        if (active) {
            const float w2v = __ldg(&tp_w2[j * 128 + d]);
            a = fmaf(wj, w2v, a);
            c = fmaf(sb[j], w2v, c);
        }
    }
    if (q) { pa[q - 1][d] = a; pc[q - 1][d] = c; }
    __syncthreads();
    if (q == 0) {
        g_A[s * 128 + d] = a + pa[0][d] + pa[1][d] + pa[2][d];
        g_C[s * 128 + d] = c + pc[0][d] + pc[1][d] + pc[2][d] + tp_b2[d];
    }
}

// =========================================================================
// Kernel 1b: transpose + bf16 hi/lo split of W1 [512,128] -> Wt [128,512].
// =========================================================================
__global__ void __launch_bounds__(256) wsplit_kernel(const float* __restrict__ w1)
{
    __shared__ float s[32][33];
    const int bx = blockIdx.x & 15;
    const int by = blockIdx.x >> 4;
    const int c = threadIdx.x & 31;
    const int r8 = threadIdx.x >> 5;
    #pragma unroll
    for (int p = 0; p < 4; p++) {
        const int r = r8 + p * 8;
        s[r][c] = w1[(bx * 32 + r) * 128 + by * 32 + c];
    }
    __syncthreads();
    #pragma unroll
    for (int p = 0; p < 4; p++) {
        const int r = r8 + p * 8;
        const int n = by * 32 + r;
        const float v = s[c][r];
        const __nv_bfloat16 hb = __float2bfloat16_rn(v);
        const float rres = v - __bfloat162float(hb);
        const __nv_bfloat16 lb = __float2bfloat16_rn(rres);
        g_Whi[n * 512 + bx * 32 + c] = __bfloat16_as_ushort(hb);
        g_Wlo[n * 512 + bx * 32 + c] = __bfloat16_as_ushort(lb);
    }
}

// =========================================================================
// Kernel 2: temporal attention encoder, online softmax, quad pipeline.
// =========================================================================
__global__ void __launch_bounds__(256, 3) encode_kernel(
    const int*   __restrict__ edge_index,
    const int*   __restrict__ ets,
    const int*   __restrict__ hnb,
    const int*   __restrict__ hts,
    const int*   __restrict__ hsg,
    const float* __restrict__ nemb,
    const float* __restrict__ semb)
{
    __shared__ float sbp[128];
    if (threadIdx.x < 128) sbp[threadIdx.x] = g_bp[threadIdx.x];
    __syncthreads();

    const int w    = threadIdx.x >> 5;
    const int lane = threadIdx.x & 31;
    const int task = blockIdx.x * 8 + w;
    const int e    = task >> 1;
    const int side = task & 1;

    const int node = edge_index[side * NB + e];
    const int qt   = ets[e];
    const float qtf = (float)qt;

    const float4* nemb4 = (const float4*)nemb;
    const float4* A4 = (const float4*)g_A;
    const float4* C4 = (const float4*)g_C;

    const float4 q4 = __ldg(&nemb4[node * 32 + lane]);
    const float4 s0 = __ldg(&((const float4*)semb)[lane]);
    const float4 s1 = __ldg(&((const float4*)semb)[32 + lane]);

    // per-lane meta: nb(17b) | seg(8b)<<17 | sg<<25 | valid<<26
    unsigned mt_l = 0;
    float    dl_l = 0.0f;
    if (lane < KN) {
        const int nb = hnb[node * KN + lane];
        const int ht = hts[node * KN + lane];
        const int sg = hsg[node * KN + lane];
        const float delta = qtf - (float)ht;
        int lo = 0, hi = 128;
        #pragma unroll
        for (int it = 0; it < 7; it++) {
            const int mid = (lo + hi) >> 1;
            if (sbp[mid] < delta) lo = mid + 1; else hi = mid;
        }
        const bool valid = (nb != -1) && (ht < qt);
        const unsigned nbc = (nb == -1) ? 0u : (unsigned)nb;
        mt_l = nbc | ((unsigned)lo << 17) | ((unsigned)sg << 25) | (valid ? (1u << 26) : 0u);
        dl_l = delta;
    }

    unsigned mt[4]; float dl[4]; float4 em[4];
    #pragma unroll
    for (int i = 0; i < 4; i++) {
        mt[i] = __shfl_sync(0xffffffffu, mt_l, i);
        dl[i] = __shfl_sync(0xffffffffu, dl_l, i);
        em[i] = __ldg(&nemb4[(mt[i] & 0x1FFFFu) * 32 + lane]);
    }

    const float rsH = 0.08838834764831845f;
    float m = -INFINITY;
    float ssum = 0.0f;
    float4 acc = make_float4(0.f, 0.f, 0.f, 0.f);

    #pragma unroll
    for (int g = 0; g < 5; g++) {
        unsigned mtn[4]; float dln[4]; float4 emn[4];
        if (g < 4) {
            #pragma unroll
            for (int i = 0; i < 4; i++) {
                const int k = (g + 1) * 4 + i;
                mtn[i] = __shfl_sync(0xffffffffu, mt_l, k);
                dln[i] = __shfl_sync(0xffffffffu, dl_l, k);
                emn[i] = __ldg(&nemb4[(mtn[i] & 0x1FFFFu) * 32 + lane]);
            }
        }

        float4 kv[4]; float dp[4];
        #pragma unroll
        for (int i = 0; i < 4; i++) {
            const int seg = (mt[i] >> 17) & 0xFF;
            const float4 sg4 = (mt[i] & (1u << 25)) ? s1 : s0;
            const float4 a4 = A4[seg * 32 + lane];
            const float4 c4 = C4[seg * 32 + lane];
            kv[i].x = em[i].x + sg4.x + fmaf(a4.x, dl[i], c4.x);
            kv[i].y = em[i].y + sg4.y + fmaf(a4.y, dl[i], c4.y);
            kv[i].z = em[i].z + sg4.z + fmaf(a4.z, dl[i], c4.z);
            kv[i].w = em[i].w + sg4.w + fmaf(a4.w, dl[i], c4.w);
            dp[i] = fmaf(kv[i].x, q4.x, fmaf(kv[i].y, q4.y,
                    fmaf(kv[i].z, q4.z, kv[i].w * q4.w)));
        }

        const float r0 = dp[0] + __shfl_xor_sync(0xffffffffu, dp[0], 16);
        const float r1 = dp[1] + __shfl_xor_sync(0xffffffffu, dp[1], 16);
        const float r2 = dp[2] + __shfl_xor_sync(0xffffffffu, dp[2], 16);
        const float r3 = dp[3] + __shfl_xor_sync(0xffffffffu, dp[3], 16);
        const float m01 = (lane & 16) ? r1 : r0;
        const float m23 = (lane & 16) ? r3 : r2;
        const float q01 = m01 + __shfl_xor_sync(0xffffffffu, m01, 8);
        const float q23 = m23 + __shfl_xor_sync(0xffffffffu, m23, 8);
        float mm = (lane & 8) ? q23 : q01;
        mm += __shfl_xor_sync(0xffffffffu, mm, 4);
        mm += __shfl_xor_sync(0xffffffffu, mm, 2);
        mm += __shfl_xor_sync(0xffffffffu, mm, 1);
        const float t0 = __shfl_sync(0xffffffffu, mm, 0);
        const float t1 = __shfl_sync(0xffffffffu, mm, 16);
        const float t2 = __shfl_sync(0xffffffffu, mm, 8);
        const float t3 = __shfl_sync(0xffffffffu, mm, 24);

        const float sc0 = (mt[0] & (1u << 26)) ? t0 * rsH : NEGV;
        const float sc1 = (mt[1] & (1u << 26)) ? t1 * rsH : NEGV;
        const float sc2 = (mt[2] & (1u << 26)) ? t2 * rsH : NEGV;
        const float sc3 = (mt[3] & (1u << 26)) ? t3 * rsH : NEGV;

        const float mn = fmaxf(m, fmaxf(fmaxf(sc0, sc1), fmaxf(sc2, sc3)));
        const float f  = __expf(m - mn);
        const float w0 = __expf(sc0 - mn);
        const float w1 = __expf(sc1 - mn);
        const float w2 = __expf(sc2 - mn);
        const float w3 = __expf(sc3 - mn);
        ssum = fmaf(ssum, f, w0 + w1 + w2 + w3);
        acc.x = fmaf(w3, kv[3].x, fmaf(w2, kv[2].x, fmaf(w1, kv[1].x, fmaf(w0, kv[0].x, acc.x * f))));
        acc.y = fmaf(w3, kv[3].y, fmaf(w2, kv[2].y, fmaf(w1, kv[1].y, fmaf(w0, kv[0].y, acc.y * f))));
        acc.z = fmaf(w3, kv[3].z, fmaf(w2, kv[2].z, fmaf(w1, kv[1].z, fmaf(w0, kv[0].z, acc.z * f))));
        acc.w = fmaf(w3, kv[3].w, fmaf(w2, kv[2].w, fmaf(w1, kv[1].w, fmaf(w0, kv[0].w, acc.w * f))));
        m = mn;

        if (g < 4) {
            #pragma unroll
            for (int i = 0; i < 4; i++) { mt[i] = mtn[i]; dl[i] = dln[i]; em[i] = emn[i]; }
        }
    }

    const float inv = 1.0f / ssum;
    acc.x *= inv; acc.y *= inv; acc.z *= inv; acc.w *= inv;
    ((float4*)g_z)[(unsigned)(side * NB + e) * 32 + lane] = acc;
}

// =========================================================================
// Kernel 3: split-bf16 mma.sync GEMM MLP, double-buffered.
// D = Fhi@Whi + Fhi@Wlo + Flo@Whi. B tiles staged via cp.async (pure copy);
// A tiles reg-prefetched + converted overlapping the MMA loop. 1 sync/chunk.
// =========================================================================
#define MMA_BF16(C, A, B0, B1) \
    asm volatile("mma.sync.aligned.m16n8k16.row.col.f32.bf16.bf16.f32 " \
        "{%0,%1,%2,%3}, {%4,%5,%6,%7}, {%8,%9}, {%0,%1,%2,%3};" \
        : "+f"((C)[0]), "+f"((C)[1]), "+f"((C)[2]), "+f"((C)[3]) \
        : "r"((A)[0]), "r"((A)[1]), "r"((A)[2]), "r"((A)[3]), "r"(B0), "r"(B1))

__device__ __forceinline__ void cp16(void* smem, const void* gmem) {
    const uint32_t s = (uint32_t)__cvta_generic_to_shared(smem);
    asm volatile("cp.async.cg.shared.global [%0], [%1], 16;"
                 :: "r"(s), "l"(__cvta_generic_to_global(gmem)) : "memory");
}
#define CP_COMMIT() asm volatile("cp.async.commit_group;" ::: "memory")
#define CP_WAIT0()  asm volatile("cp.async.wait_group 0;" ::: "memory")

#define REGION_SZ 18432           // 128 rows x 144 B
#define BUF_SZ    (4 * REGION_SZ) // Ahi, Alo, Bhi, Blo

extern __shared__ char dsm[];
__global__ void __launch_bounds__(256) mlp_mma_kernel(
    const float* __restrict__ b1,
    const float* __restrict__ w2,
    const float* __restrict__ b2,
    float*       __restrict__ out)
{
    __shared__ float slog[128];

    const int tid  = threadIdx.x;
    const int wid  = tid >> 5;
    const int lane = tid & 31;
    const int e0   = blockIdx.x * 128;

    if (tid < 128) slog[tid] = 0.0f;

    const int wm = wid >> 1;
    const int wn = wid & 1;
    const int g  = lane >> 2;
    const int t2 = (lane & 3) * 2;

    float acc[2][8][4];
    #pragma unroll
    for (int mt = 0; mt < 2; mt++)
        #pragma unroll
        for (int nt = 0; nt < 8; nt++)
            #pragma unroll
            for (int u = 0; u < 4; u++)
                acc[mt][nt][u] = 0.0f;

    const int f4 = tid & 15;
    const int r0 = tid >> 4;
    const int bn = tid >> 1;          // B stage: n row
    const int bhk = tid & 1;          // B stage: k half

    // ---- staging helpers (inline lambdas) ----
    auto loadA = [&](int chunk, float4* fv) {
        const int region = chunk >> 1;
        const int cb4 = (chunk & 1) * 16;
        #pragma unroll
        for (int p = 0; p < 8; p++) {
            const int r = r0 + p * 16;
            float4 v;
            if (region == 0) {
                v = ((const float4*)g_z)[(unsigned)(e0 + r) * 32 + cb4 + f4];
            } else if (region == 1) {
                v = ((const float4*)g_z)[(unsigned)(NB + e0 + r) * 32 + cb4 + f4];
            } else {
                const float4 a = ((const float4*)g_z)[(unsigned)(e0 + r) * 32 + cb4 + f4];
                const float4 b = ((const float4*)g_z)[(unsigned)(NB + e0 + r) * 32 + cb4 + f4];
                if (region == 2) {
                    v.x = fabsf(a.x - b.x); v.y = fabsf(a.y - b.y);
                    v.z = fabsf(a.z - b.z); v.w = fabsf(a.w - b.w);
                } else {
                    v.x = a.x * b.x; v.y = a.y * b.y;
                    v.z = a.z * b.z; v.w = a.w * b.w;
                }
            }
            fv[p] = v;
        }
    };
    auto storeA = [&](char* bufA, const float4* fv) {
        char* pAhi = bufA;
        char* pAlo = bufA + REGION_SZ;
        #pragma unroll
        for (int p = 0; p < 8; p++) {
            const int r = r0 + p * 16;
            const float4 v = fv[p];
            const __nv_bfloat16 hx = __float2bfloat16_rn(v.x);
            const __nv_bfloat16 hy = __float2bfloat16_rn(v.y);
            const __nv_bfloat16 hz = __float2bfloat16_rn(v.z);
            const __nv_bfloat16 hw = __float2bfloat16_rn(v.w);
            const __nv_bfloat16 lx = __float2bfloat16_rn(v.x - __bfloat162float(hx));
            const __nv_bfloat16 ly = __float2bfloat16_rn(v.y - __bfloat162float(hy));
            const __nv_bfloat16 lz = __float2bfloat16_rn(v.z - __bfloat162float(hz));
            const __nv_bfloat16 lw = __float2bfloat16_rn(v.w - __bfloat162float(hw));
            uint2 hv, lv;
            hv.x = (uint32_t)__bfloat16_as_ushort(hx) | ((uint32_t)__bfloat16_as_ushort(hy) << 16);
            hv.y = (uint32_t)__bfloat16_as_ushort(hz) | ((uint32_t)__bfloat16_as_ushort(hw) << 16);
            lv.x = (uint32_t)__bfloat16_as_ushort(lx) | ((uint32_t)__bfloat16_as_ushort(ly) << 16);
            lv.y = (uint32_t)__bfloat16_as_ushort(lz) | ((uint32_t)__bfloat16_as_ushort(lw) << 16);
            *(uint2*)(pAhi + r * 144 + f4 * 8) = hv;
            *(uint2*)(pAlo + r * 144 + f4 * 8) = lv;
        }
    };
    auto stageB = [&](int chunk, char* bufA) {
        char* pBhi = bufA + 2 * REGION_SZ;
        char* pBlo = bufA + 3 * REGION_SZ;
        #pragma unroll
        for (int i = 0; i < 4; i++) {
            const int kk = chunk * 64 + bhk * 32 + i * 8;
            const int so = bn * 144 + (bhk * 32 + i * 8) * 2;
            cp16(pBhi + so, &g_Whi[bn * 512 + kk]);
            cp16(pBlo + so, &g_Wlo[bn * 512 + kk]);
        }
    };

    // ---- prologue: stage chunk 0 into buffer 0 ----
    {
        float4 fv[8];
        loadA(0, fv);
        storeA(dsm, fv);
        stageB(0, dsm);
        CP_COMMIT();
        CP_WAIT0();
    }
    __syncthreads();

    for (int chunk = 0; chunk < 8; chunk++) {
        char* bufC = dsm + (chunk & 1) * BUF_SZ;      // compute buffer
        char* bufN = dsm + ((chunk & 1) ^ 1) * BUF_SZ; // next buffer

        float4 fv[8];
        if (chunk < 7) {
            stageB(chunk + 1, bufN);   // async copies, no regs
            CP_COMMIT();
            loadA(chunk + 1, fv);      // global loads in flight over MMA loop
        }

        // ---- MMA on current buffer ----
        char* sAhi = bufC;
        char* sAlo = bufC + REGION_SZ;
        char* sBhi = bufC + 2 * REGION_SZ;
        char* sBlo = bufC + 3 * REGION_SZ;
        #pragma unroll
        for (int ks = 0; ks < 4; ks++) {
            const int cA = (ks * 16 + t2) * 2;
            uint32_t ah[2][4], al[2][4];
            #pragma unroll
            for (int mt = 0; mt < 2; mt++) {
                const int row = wm * 32 + mt * 16 + g;
                ah[mt][0] = *(const uint32_t*)(sAhi + row * 144 + cA);
                ah[mt][1] = *(const uint32_t*)(sAhi + (row + 8) * 144 + cA);
                ah[mt][2] = *(const uint32_t*)(sAhi + row * 144 + cA + 16);
                ah[mt][3] = *(const uint32_t*)(sAhi + (row + 8) * 144 + cA + 16);
                al[mt][0] = *(const uint32_t*)(sAlo + row * 144 + cA);
                al[mt][1] = *(const uint32_t*)(sAlo + (row + 8) * 144 + cA);
                al[mt][2] = *(const uint32_t*)(sAlo + row * 144 + cA + 16);
                al[mt][3] = *(const uint32_t*)(sAlo + (row + 8) * 144 + cA + 16);
            }
            #pragma unroll
            for (int nt = 0; nt < 8; nt++) {
                const int n = wn * 64 + nt * 8 + g;
                const uint32_t bh0 = *(const uint32_t*)(sBhi + n * 144 + cA);
                const uint32_t bh1 = *(const uint32_t*)(sBhi + n * 144 + cA + 16);
                const uint32_t bl0 = *(const uint32_t*)(sBlo + n * 144 + cA);
                const uint32_t bl1 = *(const uint32_t*)(sBlo + n * 144 + cA + 16);
                #pragma unroll
                for (int mt = 0; mt < 2; mt++) {
                    MMA_BF16(acc[mt][nt], ah[mt], bh0, bh1);
                    MMA_BF16(acc[mt][nt], ah[mt], bl0, bl1);
                    MMA_BF16(acc[mt][nt], al[mt], bh0, bh1);
                }
            }
        }

        if (chunk < 7) {
            storeA(bufN, fv);
            CP_WAIT0();
        }
        __syncthreads();
    }

    // ---- epilogue ----
    float b1v[16], w2v[16];
    #pragma unroll
    for (int nt = 0; nt < 8; nt++) {
        const int n = wn * 64 + nt * 8 + t2;
        b1v[nt * 2]     = __ldg(&b1[n]);
        b1v[nt * 2 + 1] = __ldg(&b1[n + 1]);
        w2v[nt * 2]     = __ldg(&w2[n]);
        w2v[nt * 2 + 1] = __ldg(&w2[n + 1]);
    }
    #pragma unroll
    for (int mt = 0; mt < 2; mt++) {
        float p1 = 0.0f, p2 = 0.0f;
        #pragma unroll
        for (int nt = 0; nt < 8; nt++) {
            p1 += fmaxf(acc[mt][nt][0] + b1v[2 * nt],     0.0f) * w2v[2 * nt]
                + fmaxf(acc[mt][nt][1] + b1v[2 * nt + 1], 0.0f) * w2v[2 * nt + 1];
            p2 += fmaxf(acc[mt][nt][2] + b1v[2 * nt],     0.0f) * w2v[2 * nt]
                + fmaxf(acc[mt][nt][3] + b1v[2 * nt + 1], 0.0f) * w2v[2 * nt + 1];
        }
        const int r1 = wm * 32 + mt * 16 + g;
        atomicAdd(&slog[r1], p1);
        atomicAdd(&slog[r1 + 8], p2);
    }
    __syncthreads();
    if (tid < 128) out[e0 + tid] = slog[tid] + b2[0];
}

// =========================================================================
extern "C" void kernel_launch(void* const* d_in, const int* in_sizes, int n_in,
                              void* d_out, int out_size)
{
    const int*   edge_index = (const int*)  d_in[0];
    const int*   ets        = (const int*)  d_in[1];
    const int*   hnb        = (const int*)  d_in[2];
    const int*   hts        = (const int*)  d_in[3];
    const int*   hsg        = (const int*)  d_in[4];
    const float* nemb       = (const float*)d_in[5];
    const float* semb       = (const float*)d_in[6];
    const float* tp_w1      = (const float*)d_in[7];
    const float* tp_b1      = (const float*)d_in[8];
    const float* tp_w2      = (const float*)d_in[9];
    const float* tp_b2      = (const float*)d_in[10];
    const float* em_w1      = (const float*)d_in[11];
    const float* em_b1      = (const float*)d_in[12];
    const float* em_w2      = (const float*)d_in[13];
    const float* em_b2      = (const float*)d_in[14];
    float* out = (float*)d_out;

    cudaFuncSetAttribute(mlp_mma_kernel,
                         cudaFuncAttributeMaxDynamicSharedMemorySize, 2 * BUF_SZ);

    precompute_kernel<<<129, 512>>>(tp_w1, tp_b1, tp_w2, tp_b2);
    wsplit_kernel<<<64, 256>>>(em_w1);
    encode_kernel<<<(2 * NB) / 8, 256>>>(edge_index, ets, hnb, hts, hsg, nemb, semb);
    mlp_mma_kernel<<<NB / 128, 256, 2 * BUF_SZ>>>(em_b1, em_w2, em_b2, out);
}